// round 1
// baseline (speedup 1.0000x reference)
#include <cuda_runtime.h>
#include <cuda_bf16.h>
#include <math.h>

// ---------------- problem constants ----------------
#define BB    32
#define HH    56
#define WW    56
#define CC    256
#define WIN   7
#define SHIFT 3
#define HEADS 8
#define HD    32          // head dim
#define NN    49          // win*win
#define NWIN  64          // (56/7)^2
#define BWIN  (BB*NWIN)   // 2048 windows
#define NTOK  (BWIN*NN)   // 100352 tokens
#define LL    (HH*WW)     // 3136

// ---------------- scratch (device globals; no allocs allowed) ----------------
__device__ float g_xw  [(size_t)NTOK*CC];      // LN1 + shifted + windowed input
__device__ float g_qkv [(size_t)NTOK*3*CC];    // qkv gemm out
__device__ float g_obuf[(size_t)NTOK*CC];      // attention out (B_,N,H,d)->C
__device__ float g_x2  [(size_t)BB*LL*CC];     // after attn residual
__device__ float g_xn2 [(size_t)NTOK*CC];      // LN2 out
__device__ float g_h1  [(size_t)NTOK*4*CC];    // fc1+gelu out

// ---------------- helpers ----------------
__device__ __forceinline__ float warp_sum(float v) {
#pragma unroll
    for (int o = 16; o; o >>= 1) v += __shfl_xor_sync(0xffffffffu, v, o);
    return v;
}
__device__ __forceinline__ float warp_max(float v) {
#pragma unroll
    for (int o = 16; o; o >>= 1) v = fmaxf(v, __shfl_xor_sync(0xffffffffu, v, o));
    return v;
}

// token (window-order) -> source row in (b, H, W) image space after reverse shift
__device__ __forceinline__ int tok_to_imgrow(int tok) {
    int n  = tok % NN;
    int bw = tok / NN;
    int b  = bw >> 6;          // /64
    int w  = bw & 63;
    int hs = (w >> 3) * WIN + n / WIN;
    int ws = (w & 7)  * WIN + n % WIN;
    int h0 = hs + SHIFT; if (h0 >= HH) h0 -= HH;
    int w0 = ws + SHIFT; if (w0 >= WW) w0 -= WW;
    return b * LL + h0 * WW + w0;
}

// ---------------- K1: LN1 + shift + window partition (warp per token) -------
__global__ void ln1_window_kernel(const float* __restrict__ x,
                                  const float* __restrict__ g,
                                  const float* __restrict__ b,
                                  float* __restrict__ xw) {
    int tok  = blockIdx.x * 8 + (threadIdx.x >> 5);
    int lane = threadIdx.x & 31;
    if (tok >= NTOK) return;
    const float* row = x + (size_t)tok_to_imgrow(tok) * CC;
    float vals[8], s = 0.f;
#pragma unroll
    for (int q = 0; q < 8; q++) { vals[q] = row[lane + 32 * q]; s += vals[q]; }
    float mean = warp_sum(s) * (1.f / CC);
    float vv = 0.f;
#pragma unroll
    for (int q = 0; q < 8; q++) { float d = vals[q] - mean; vv += d * d; }
    float var = warp_sum(vv) * (1.f / CC);
    float inv = rsqrtf(var + 1e-5f);
    float* out = xw + (size_t)tok * CC;
#pragma unroll
    for (int q = 0; q < 8; q++) {
        int c = lane + 32 * q;
        out[c] = (vals[q] - mean) * inv * g[c] + b[c];
    }
}

// ---------------- K5a: LN2 (warp per token, identity token order) -----------
__global__ void ln2_kernel(const float* __restrict__ x,
                           const float* __restrict__ g,
                           const float* __restrict__ b,
                           float* __restrict__ out_) {
    int tok  = blockIdx.x * 8 + (threadIdx.x >> 5);
    int lane = threadIdx.x & 31;
    if (tok >= NTOK) return;
    const float* row = x + (size_t)tok * CC;
    float vals[8], s = 0.f;
#pragma unroll
    for (int q = 0; q < 8; q++) { vals[q] = row[lane + 32 * q]; s += vals[q]; }
    float mean = warp_sum(s) * (1.f / CC);
    float vv = 0.f;
#pragma unroll
    for (int q = 0; q < 8; q++) { float d = vals[q] - mean; vv += d * d; }
    float var = warp_sum(vv) * (1.f / CC);
    float inv = rsqrtf(var + 1e-5f);
    float* out = out_ + (size_t)tok * CC;
#pragma unroll
    for (int q = 0; q < 8; q++) {
        int c = lane + 32 * q;
        out[c] = (vals[q] - mean) * inv * g[c] + b[c];
    }
}

// ---------------- tiled SGEMM: C = A @ W^T + bias, with epilogues -----------
// MODE 0: plain (+bias)                    -> C[m*N+n]
// MODE 1: +bias, exact GELU                -> C[m*N+n]
// MODE 2: +bias, + res[m*N+n]              -> C[m*N+n]
// MODE 3: +bias, scatter row (window rev + unshift), + res[r*N+n] -> C[r*N+n]
#define GBM 128
#define GBN 128
#define GBK 8
template <int MODE>
__global__ __launch_bounds__(256)
void gemm_kernel(const float* __restrict__ A, const float* __restrict__ W,
                 const float* __restrict__ bias, float* __restrict__ C,
                 int M, int N, int K, const float* __restrict__ res) {
    __shared__ float As[GBK][GBM];
    __shared__ float Bs[GBK][GBN];
    int tid = threadIdx.x;
    int tx = tid & 15, ty = tid >> 4;
    int m0 = blockIdx.y * GBM, n0 = blockIdx.x * GBN;

    int lrow  = tid >> 1;          // 0..127
    int lpart = (tid & 1) * 4;     // 0 or 4
    const float* Aptr = A + (size_t)(m0 + lrow) * K + lpart;
    const float* Wptr = W + (size_t)(n0 + lrow) * K + lpart;

    float acc[8][8];
#pragma unroll
    for (int i = 0; i < 8; i++)
#pragma unroll
        for (int j = 0; j < 8; j++) acc[i][j] = 0.f;

    for (int k0 = 0; k0 < K; k0 += GBK) {
        float4 a4 = *(const float4*)(Aptr + k0);
        float4 w4 = *(const float4*)(Wptr + k0);
        As[lpart + 0][lrow] = a4.x; As[lpart + 1][lrow] = a4.y;
        As[lpart + 2][lrow] = a4.z; As[lpart + 3][lrow] = a4.w;
        Bs[lpart + 0][lrow] = w4.x; Bs[lpart + 1][lrow] = w4.y;
        Bs[lpart + 2][lrow] = w4.z; Bs[lpart + 3][lrow] = w4.w;
        __syncthreads();
#pragma unroll
        for (int kk = 0; kk < GBK; kk++) {
            float ra[8], rb[8];
#pragma unroll
            for (int i = 0; i < 8; i++) ra[i] = As[kk][ty * 8 + i];
#pragma unroll
            for (int j = 0; j < 8; j++) rb[j] = Bs[kk][tx * 8 + j];
#pragma unroll
            for (int i = 0; i < 8; i++)
#pragma unroll
                for (int j = 0; j < 8; j++) acc[i][j] += ra[i] * rb[j];
        }
        __syncthreads();
    }

#pragma unroll
    for (int i = 0; i < 8; i++) {
        int m = m0 + ty * 8 + i;
        size_t rout = (size_t)m;
        if (MODE == 3) rout = (size_t)tok_to_imgrow(m);
#pragma unroll
        for (int j = 0; j < 8; j++) {
            int n = n0 + tx * 8 + j;
            float v = acc[i][j] + bias[n];
            if (MODE == 1) v = 0.5f * v * (1.f + erff(v * 0.7071067811865476f));
            if (MODE == 2) v += res[(size_t)m * N + n];
            if (MODE == 3) v += res[rout * N + n];
            C[rout * N + n] = v;
        }
    }
}

// ---------------- K3: windowed attention, triple softmax --------------------
// one block per (window b_, head h); 256 threads
#define QP 33   // padded stride to avoid bank conflicts
__global__ __launch_bounds__(256)
void attn_kernel(const float* __restrict__ qkv,
                 const float* __restrict__ rpb_table,
                 const float* __restrict__ attn_mask,
                 const float* __restrict__ sal_fg,
                 const float* __restrict__ sal_bg,
                 float* __restrict__ obuf) {
    int bw = blockIdx.x;       // window 0..2047
    int h  = blockIdx.y;       // head 0..7
    int tid  = threadIdx.x;
    int lane = tid & 31;
    int warp = tid >> 5;

    __shared__ float qs[NN * QP];
    __shared__ float ks[NN * QP];
    __shared__ float vs[NN * QP];
    __shared__ float sc[NN * NN];
    __shared__ float rpb_s[169];
    __shared__ float fg_s[NN], bg_s[NN];

    const float* base = qkv + (size_t)bw * NN * (3 * CC);
    const float scale = 0.17677669529663687f;   // 1/sqrt(32)
    for (int t = tid; t < NN * HD; t += 256) {
        int n = t >> 5, dd = t & 31;
        qs[n * QP + dd] = base[n * 768 +            h * HD + dd] * scale;
        ks[n * QP + dd] = base[n * 768 + CC       + h * HD + dd];
        vs[n * QP + dd] = base[n * 768 + 2 * CC   + h * HD + dd];
    }
    if (tid < 169) rpb_s[tid] = rpb_table[tid * HEADS + h];
    if (tid < NN) {
        fg_s[tid] = sal_fg[(size_t)bw * (NN * NN) + tid];   // row-constant mask
        bg_s[tid] = sal_bg[(size_t)bw * (NN * NN) + tid];
    }
    __syncthreads();

    int w = bw & 63;
    const float* am = attn_mask + (size_t)w * (NN * NN);
    for (int t = tid; t < NN * NN; t += 256) {
        int i = t / NN, j = t - i * NN;
        float s = 0.f;
        const float* qi = qs + i * QP;
        const float* kj = ks + j * QP;
#pragma unroll
        for (int dd = 0; dd < HD; dd++) s += qi[dd] * kj[dd];
        int dy = i / WIN - j / WIN + (WIN - 1);
        int dx = i % WIN - j % WIN + (WIN - 1);
        sc[t] = s + rpb_s[dy * (2 * WIN - 1) + dx] + am[t];
    }
    __syncthreads();

    // warp per row: 3 softmaxes, combine p + p_fg - p_bg in place
    for (int i = warp; i < NN; i += 8) {
        float* rowp = sc + i * NN;
        float a0 = rowp[lane];
        bool v1  = (lane + 32) < NN;
        float a1 = v1 ? rowp[lane + 32] : -1e30f;
        float f0 = fg_s[lane], b0m = bg_s[lane];
        float f1 = v1 ? fg_s[lane + 32] : 0.f;
        float b1m = v1 ? bg_s[lane + 32] : 0.f;

        float m1 = warp_max(fmaxf(a0, a1));
        float m2 = warp_max(fmaxf(a0 + f0, v1 ? a1 + f1 : -1e30f));
        float m3 = warp_max(fmaxf(a0 + b0m, v1 ? a1 + b1m : -1e30f));

        float e1a = __expf(a0 - m1),        e1b = v1 ? __expf(a1 - m1) : 0.f;
        float e2a = __expf(a0 + f0 - m2),   e2b = v1 ? __expf(a1 + f1 - m2) : 0.f;
        float e3a = __expf(a0 + b0m - m3),  e3b = v1 ? __expf(a1 + b1m - m3) : 0.f;

        float s1 = warp_sum(e1a + e1b);
        float s2 = warp_sum(e2a + e2b);
        float s3 = warp_sum(e3a + e3b);
        float i1 = 1.f / s1, i2 = 1.f / s2, i3 = 1.f / s3;

        rowp[lane] = e1a * i1 + e2a * i2 - e3a * i3;
        if (v1) rowp[lane + 32] = e1b * i1 + e2b * i2 - e3b * i3;
    }
    __syncthreads();

    // O = P @ V   (o stored (B_,N,H,d) -> contiguous C)
    for (int t = tid; t < NN * HD; t += 256) {
        int i = t >> 5, dd = t & 31;
        const float* wrow = sc + i * NN;
        float acc = 0.f;
#pragma unroll
        for (int j = 0; j < NN; j++) acc += wrow[j] * vs[j * QP + dd];
        obuf[((size_t)bw * NN + i) * CC + h * HD + dd] = acc;
    }
}

// ---------------- launch ----------------
extern "C" void kernel_launch(void* const* d_in, const int* in_sizes, int n_in,
                              void* d_out, int out_size) {
    const float* x       = (const float*)d_in[0];
    const float* qkv_w   = (const float*)d_in[1];
    const float* qkv_b   = (const float*)d_in[2];
    const float* rpb_tab = (const float*)d_in[3];
    const float* proj_w  = (const float*)d_in[4];
    const float* proj_b  = (const float*)d_in[5];
    const float* n1g     = (const float*)d_in[6];
    const float* n1b     = (const float*)d_in[7];
    const float* n2g     = (const float*)d_in[8];
    const float* n2b     = (const float*)d_in[9];
    const float* fc1_w   = (const float*)d_in[10];
    const float* fc1_b   = (const float*)d_in[11];
    const float* fc2_w   = (const float*)d_in[12];
    const float* fc2_b   = (const float*)d_in[13];
    const float* amask   = (const float*)d_in[14];
    const float* sal_fg  = (const float*)d_in[15];
    const float* sal_bg  = (const float*)d_in[16];
    float* out = (float*)d_out;

    float *xw, *qkvb, *obuf, *x2, *xn2, *h1;
    cudaGetSymbolAddress((void**)&xw,   g_xw);
    cudaGetSymbolAddress((void**)&qkvb, g_qkv);
    cudaGetSymbolAddress((void**)&obuf, g_obuf);
    cudaGetSymbolAddress((void**)&x2,   g_x2);
    cudaGetSymbolAddress((void**)&xn2,  g_xn2);
    cudaGetSymbolAddress((void**)&h1,   g_h1);

    // 1) LN1 + shift + window partition
    ln1_window_kernel<<<NTOK / 8, 256>>>(x, n1g, n1b, xw);

    // 2) qkv = xw @ qkv_w^T + b        (M=100352, N=768, K=256)
    gemm_kernel<0><<<dim3(768 / GBN, NTOK / GBM), 256>>>(xw, qkv_w, qkv_b, qkvb,
                                                         NTOK, 768, CC, nullptr);

    // 3) attention (2048 windows x 8 heads)
    attn_kernel<<<dim3(BWIN, HEADS), 256>>>(qkvb, rpb_tab, amask, sal_fg, sal_bg, obuf);

    // 4) proj + window reverse + unshift + shortcut residual -> x2
    gemm_kernel<3><<<dim3(CC / GBN, NTOK / GBM), 256>>>(obuf, proj_w, proj_b, x2,
                                                        NTOK, CC, CC, x);

    // 5) LN2
    ln2_kernel<<<NTOK / 8, 256>>>(x2, n2g, n2b, xn2);

    // 6) fc1 + GELU     (N=1024, K=256)
    gemm_kernel<1><<<dim3(1024 / GBN, NTOK / GBM), 256>>>(xn2, fc1_w, fc1_b, h1,
                                                          NTOK, 1024, CC, nullptr);

    // 7) fc2 + residual -> out  (N=256, K=1024)
    gemm_kernel<2><<<dim3(CC / GBN, NTOK / GBM), 256>>>(h1, fc2_w, fc2_b, out,
                                                        NTOK, CC, 1024, x2);
}

// round 4
// speedup vs baseline: 2.4006x; 2.4006x over previous
#include <cuda_runtime.h>
#include <cuda_bf16.h>
#include <math.h>
#include <cstdint>

// ---------------- problem constants ----------------
#define BB    32
#define HH    56
#define WW    56
#define CC    256
#define WIN   7
#define SHIFT 3
#define HEADS 8
#define HD    32
#define NN    49
#define NWIN  64
#define BWIN  (BB*NWIN)   // 2048
#define NTOK  (BWIN*NN)   // 100352
#define LL    (HH*WW)     // 3136

// ---------------- scratch ----------------
__device__ float g_xw  [(size_t)NTOK*CC];
__device__ float g_qkv [(size_t)NTOK*3*CC];
__device__ float g_obuf[(size_t)NTOK*CC];
__device__ float g_x2  [(size_t)BB*LL*CC];
__device__ float g_xn2 [(size_t)NTOK*CC];
__device__ float g_h1  [(size_t)NTOK*4*CC];

// ---------------- helpers ----------------
__device__ __forceinline__ float warp_sum(float v) {
#pragma unroll
    for (int o = 16; o; o >>= 1) v += __shfl_xor_sync(0xffffffffu, v, o);
    return v;
}
__device__ __forceinline__ float warp_max(float v) {
#pragma unroll
    for (int o = 16; o; o >>= 1) v = fmaxf(v, __shfl_xor_sync(0xffffffffu, v, o));
    return v;
}
__device__ __forceinline__ uint32_t smem_u32(const void* p) {
    uint32_t a;
    asm("{ .reg .u64 t; cvta.to.shared.u64 t, %1; cvt.u32.u64 %0, t; }" : "=r"(a) : "l"(p));
    return a;
}
__device__ __forceinline__ uint32_t cvt_tf32(float f) {
    uint32_t u; asm("cvt.rna.tf32.f32 %0, %1;" : "=r"(u) : "f"(f)); return u;
}
__device__ __forceinline__ int tok_to_imgrow(int tok) {
    int n  = tok % NN;
    int bw = tok / NN;
    int b  = bw >> 6;
    int w  = bw & 63;
    int hs = (w >> 3) * WIN + n / WIN;
    int ws = (w & 7)  * WIN + n % WIN;
    int h0 = hs + SHIFT; if (h0 >= HH) h0 -= HH;
    int w0 = ws + SHIFT; if (w0 >= WW) w0 -= WW;
    return b * LL + h0 * WW + w0;
}

#define CP_ASYNC16(dst, src) \
    asm volatile("cp.async.cg.shared.global [%0], [%1], 16;" :: "r"(dst), "l"(src))
#define CP_COMMIT() asm volatile("cp.async.commit_group;" ::: "memory")
#define CP_WAIT(n)  asm volatile("cp.async.wait_group %0;" :: "n"(n) : "memory")

__device__ __forceinline__ void mma_tf32(float* c, const uint32_t* a, const uint32_t* b) {
    asm volatile(
        "mma.sync.aligned.m16n8k8.row.col.f32.tf32.tf32.f32 "
        "{%0,%1,%2,%3}, {%4,%5,%6,%7}, {%8,%9}, {%0,%1,%2,%3};"
        : "+f"(c[0]), "+f"(c[1]), "+f"(c[2]), "+f"(c[3])
        : "r"(a[0]), "r"(a[1]), "r"(a[2]), "r"(a[3]), "r"(b[0]), "r"(b[1]));
}

// ---------------- LN kernels ----------------
__global__ void ln1_window_kernel(const float* __restrict__ x,
                                  const float* __restrict__ g,
                                  const float* __restrict__ b,
                                  float* __restrict__ xw) {
    int tok  = blockIdx.x * 8 + (threadIdx.x >> 5);
    int lane = threadIdx.x & 31;
    if (tok >= NTOK) return;
    const float* row = x + (size_t)tok_to_imgrow(tok) * CC;
    float vals[8], s = 0.f;
#pragma unroll
    for (int q = 0; q < 8; q++) { vals[q] = row[lane + 32 * q]; s += vals[q]; }
    float mean = warp_sum(s) * (1.f / CC);
    float vv = 0.f;
#pragma unroll
    for (int q = 0; q < 8; q++) { float d = vals[q] - mean; vv += d * d; }
    float inv = rsqrtf(warp_sum(vv) * (1.f / CC) + 1e-5f);
    float* out = xw + (size_t)tok * CC;
#pragma unroll
    for (int q = 0; q < 8; q++) {
        int c = lane + 32 * q;
        out[c] = (vals[q] - mean) * inv * g[c] + b[c];
    }
}
__global__ void ln2_kernel(const float* __restrict__ x,
                           const float* __restrict__ g,
                           const float* __restrict__ b,
                           float* __restrict__ out_) {
    int tok  = blockIdx.x * 8 + (threadIdx.x >> 5);
    int lane = threadIdx.x & 31;
    if (tok >= NTOK) return;
    const float* row = x + (size_t)tok * CC;
    float vals[8], s = 0.f;
#pragma unroll
    for (int q = 0; q < 8; q++) { vals[q] = row[lane + 32 * q]; s += vals[q]; }
    float mean = warp_sum(s) * (1.f / CC);
    float vv = 0.f;
#pragma unroll
    for (int q = 0; q < 8; q++) { float d = vals[q] - mean; vv += d * d; }
    float inv = rsqrtf(warp_sum(vv) * (1.f / CC) + 1e-5f);
    float* out = out_ + (size_t)tok * CC;
#pragma unroll
    for (int q = 0; q < 8; q++) {
        int c = lane + 32 * q;
        out[c] = (vals[q] - mean) * inv * g[c] + b[c];
    }
}

// ---------------- tf32 mma.sync GEMM: C = A @ W^T + bias ----------------
// MODE 0 plain | 1 GELU | 2 +res | 3 scatter(window-reverse)+res
#define TM 128
#define TN 128
#define TK 32
#define SPAD 36                         // padded k-stride (floats)
#define A_BYTES (TM * SPAD * 4)         // 18432
#define STAGE_BYTES (2 * A_BYTES)       // A + B
#define GEMM_SMEM_BYTES (2 * STAGE_BYTES)

template <int MODE>
__global__ __launch_bounds__(256, 1)
void gemm_tc(const float* __restrict__ A, const float* __restrict__ W,
             const float* __restrict__ bias, float* __restrict__ C,
             int M, int N, int K, const float* __restrict__ res) {
    extern __shared__ __align__(128) char smem[];
    uint32_t sb = smem_u32(smem);
    int tid = threadIdx.x, wid = tid >> 5, lane = tid & 31;
    int wm = wid >> 2, wn = wid & 3;          // 2 x 4 warp grid
    int m0 = blockIdx.y * TM, n0 = blockIdx.x * TN;

    float acc[4][4][4];
#pragma unroll
    for (int i = 0; i < 4; i++)
#pragma unroll
        for (int j = 0; j < 4; j++)
#pragma unroll
            for (int r = 0; r < 4; r++) acc[i][j][r] = 0.f;

    // global load mapping: 4 rows per thread (A and B tiles 128x32)
    int lrow = tid >> 3;            // 0..31
    int lc4  = tid & 7;             // float4 index along k
    const float* gA = A + (size_t)(m0 + lrow) * K + lc4 * 4;
    const float* gW = W + (size_t)(n0 + lrow) * K + lc4 * 4;
    uint32_t dA = sb + lrow * (SPAD * 4) + lc4 * 16;
    uint32_t dB = dA + A_BYTES;

    int KT = K / TK;
    // prologue: stage 0
#pragma unroll
    for (int p = 0; p < 4; p++) {
        CP_ASYNC16(dA + p * 32 * (SPAD * 4), gA + (size_t)p * 32 * K);
        CP_ASYNC16(dB + p * 32 * (SPAD * 4), gW + (size_t)p * 32 * K);
    }
    CP_COMMIT();

#pragma unroll 1
    for (int kt = 0; kt < KT; kt++) {
        bool more = (kt + 1 < KT);
        if (more) {
            uint32_t off = ((kt + 1) & 1) * STAGE_BYTES;
            const float* sA = gA + (size_t)(kt + 1) * TK;
            const float* sW = gW + (size_t)(kt + 1) * TK;
#pragma unroll
            for (int p = 0; p < 4; p++) {
                CP_ASYNC16(dA + off + p * 32 * (SPAD * 4), sA + (size_t)p * 32 * K);
                CP_ASYNC16(dB + off + p * 32 * (SPAD * 4), sW + (size_t)p * 32 * K);
            }
            CP_COMMIT();
            CP_WAIT(1);
        } else {
            CP_WAIT(0);
        }
        __syncthreads();

        const float* As = (const float*)(smem + (kt & 1) * STAGE_BYTES);
        const float* Bs = (const float*)(smem + (kt & 1) * STAGE_BYTES + A_BYTES);
#pragma unroll
        for (int ks = 0; ks < 4; ks++) {
            int k0 = ks * 8 + (lane & 3);
            uint32_t af[4][4], bf[4][2];
#pragma unroll
            for (int i = 0; i < 4; i++) {
                int r = wm * 64 + i * 16 + (lane >> 2);
                af[i][0] = cvt_tf32(As[r * SPAD + k0]);
                af[i][1] = cvt_tf32(As[(r + 8) * SPAD + k0]);
                af[i][2] = cvt_tf32(As[r * SPAD + k0 + 4]);
                af[i][3] = cvt_tf32(As[(r + 8) * SPAD + k0 + 4]);
            }
#pragma unroll
            for (int j = 0; j < 4; j++) {
                int c = wn * 32 + j * 8 + (lane >> 2);
                bf[j][0] = cvt_tf32(Bs[c * SPAD + k0]);
                bf[j][1] = cvt_tf32(Bs[c * SPAD + k0 + 4]);
            }
#pragma unroll
            for (int i = 0; i < 4; i++)
#pragma unroll
                for (int j = 0; j < 4; j++)
                    mma_tf32(acc[i][j], af[i], bf[j]);
        }
        __syncthreads();
    }

    // epilogue: write C fragments directly
#pragma unroll
    for (int i = 0; i < 4; i++) {
#pragma unroll
        for (int half = 0; half < 2; half++) {
            int m = m0 + wm * 64 + i * 16 + (lane >> 2) + half * 8;
            size_t rout = (size_t)m;
            if (MODE == 3) rout = (size_t)tok_to_imgrow(m);
#pragma unroll
            for (int j = 0; j < 4; j++) {
                int col = n0 + wn * 32 + j * 8 + 2 * (lane & 3);
                float v0 = acc[i][j][half * 2 + 0] + bias[col];
                float v1 = acc[i][j][half * 2 + 1] + bias[col + 1];
                if (MODE == 1) {
                    v0 = 0.5f * v0 * (1.f + erff(v0 * 0.7071067811865476f));
                    v1 = 0.5f * v1 * (1.f + erff(v1 * 0.7071067811865476f));
                }
                if (MODE == 2) {
                    v0 += res[(size_t)m * N + col];
                    v1 += res[(size_t)m * N + col + 1];
                }
                if (MODE == 3) {
                    v0 += res[rout * N + col];
                    v1 += res[rout * N + col + 1];
                }
                *(float2*)(C + rout * N + col) = make_float2(v0, v1);
            }
        }
    }
}

// ---------------- K3: windowed attention, triple softmax --------------------
#define QP 33
__global__ __launch_bounds__(256)
void attn_kernel(const float* __restrict__ qkv,
                 const float* __restrict__ rpb_table,
                 const float* __restrict__ attn_mask,
                 const float* __restrict__ sal_fg,
                 const float* __restrict__ sal_bg,
                 float* __restrict__ obuf) {
    int bw = blockIdx.x;
    int h  = blockIdx.y;
    int tid  = threadIdx.x;
    int lane = tid & 31;
    int warp = tid >> 5;

    __shared__ float qs[NN * QP];
    __shared__ float ks[NN * QP];
    __shared__ float vs[NN * QP];
    __shared__ float sc[NN * NN];
    __shared__ float rpb_s[169];
    __shared__ float fg_s[NN], bg_s[NN];

    const float* base = qkv + (size_t)bw * NN * (3 * CC);
    const float scale = 0.17677669529663687f;
    for (int t = tid; t < NN * HD; t += 256) {
        int n = t >> 5, dd = t & 31;
        qs[n * QP + dd] = base[n * 768 +          h * HD + dd] * scale;
        ks[n * QP + dd] = base[n * 768 + CC     + h * HD + dd];
        vs[n * QP + dd] = base[n * 768 + 2 * CC + h * HD + dd];
    }
    if (tid < 169) rpb_s[tid] = rpb_table[tid * HEADS + h];
    if (tid < NN) {
        fg_s[tid] = sal_fg[(size_t)bw * (NN * NN) + tid];
        bg_s[tid] = sal_bg[(size_t)bw * (NN * NN) + tid];
    }
    __syncthreads();

    int w = bw & 63;
    const float* am = attn_mask + (size_t)w * (NN * NN);
    for (int t = tid; t < NN * NN; t += 256) {
        int i = t / NN, j = t - i * NN;
        float s = 0.f;
        const float* qi = qs + i * QP;
        const float* kj = ks + j * QP;
#pragma unroll
        for (int dd = 0; dd < HD; dd++) s += qi[dd] * kj[dd];
        int dy = i / WIN - j / WIN + (WIN - 1);
        int dx = i % WIN - j % WIN + (WIN - 1);
        sc[t] = s + rpb_s[dy * (2 * WIN - 1) + dx] + am[t];
    }
    __syncthreads();

    for (int i = warp; i < NN; i += 8) {
        float* rowp = sc + i * NN;
        float a0 = rowp[lane];
        bool v1  = (lane + 32) < NN;
        float a1 = v1 ? rowp[lane + 32] : -1e30f;
        float f0 = fg_s[lane], b0m = bg_s[lane];
        float f1 = v1 ? fg_s[lane + 32] : 0.f;
        float b1m = v1 ? bg_s[lane + 32] : 0.f;

        float m1 = warp_max(fmaxf(a0, a1));
        float m2 = warp_max(fmaxf(a0 + f0, v1 ? a1 + f1 : -1e30f));
        float m3 = warp_max(fmaxf(a0 + b0m, v1 ? a1 + b1m : -1e30f));

        float e1a = __expf(a0 - m1),       e1b = v1 ? __expf(a1 - m1) : 0.f;
        float e2a = __expf(a0 + f0 - m2),  e2b = v1 ? __expf(a1 + f1 - m2) : 0.f;
        float e3a = __expf(a0 + b0m - m3), e3b = v1 ? __expf(a1 + b1m - m3) : 0.f;

        float i1 = 1.f / warp_sum(e1a + e1b);
        float i2 = 1.f / warp_sum(e2a + e2b);
        float i3 = 1.f / warp_sum(e3a + e3b);

        rowp[lane] = e1a * i1 + e2a * i2 - e3a * i3;
        if (v1) rowp[lane + 32] = e1b * i1 + e2b * i2 - e3b * i3;
    }
    __syncthreads();

    for (int t = tid; t < NN * HD; t += 256) {
        int i = t >> 5, dd = t & 31;
        const float* wrow = sc + i * NN;
        float acc = 0.f;
#pragma unroll
        for (int j = 0; j < NN; j++) acc += wrow[j] * vs[j * QP + dd];
        obuf[((size_t)bw * NN + i) * CC + h * HD + dd] = acc;
    }
}

// ---------------- launch ----------------
extern "C" void kernel_launch(void* const* d_in, const int* in_sizes, int n_in,
                              void* d_out, int out_size) {
    const float* x       = (const float*)d_in[0];
    const float* qkv_w   = (const float*)d_in[1];
    const float* qkv_b   = (const float*)d_in[2];
    const float* rpb_tab = (const float*)d_in[3];
    const float* proj_w  = (const float*)d_in[4];
    const float* proj_b  = (const float*)d_in[5];
    const float* n1g     = (const float*)d_in[6];
    const float* n1b     = (const float*)d_in[7];
    const float* n2g     = (const float*)d_in[8];
    const float* n2b     = (const float*)d_in[9];
    const float* fc1_w   = (const float*)d_in[10];
    const float* fc1_b   = (const float*)d_in[11];
    const float* fc2_w   = (const float*)d_in[12];
    const float* fc2_b   = (const float*)d_in[13];
    const float* amask   = (const float*)d_in[14];
    const float* sal_fg  = (const float*)d_in[15];
    const float* sal_bg  = (const float*)d_in[16];
    float* out = (float*)d_out;

    float *xw, *qkvb, *obuf, *x2, *xn2, *h1;
    cudaGetSymbolAddress((void**)&xw,   g_xw);
    cudaGetSymbolAddress((void**)&qkvb, g_qkv);
    cudaGetSymbolAddress((void**)&obuf, g_obuf);
    cudaGetSymbolAddress((void**)&x2,   g_x2);
    cudaGetSymbolAddress((void**)&xn2,  g_xn2);
    cudaGetSymbolAddress((void**)&h1,   g_h1);

    static bool attr_done = false;
    if (!attr_done) {
        cudaFuncSetAttribute(gemm_tc<0>, cudaFuncAttributeMaxDynamicSharedMemorySize, GEMM_SMEM_BYTES);
        cudaFuncSetAttribute(gemm_tc<1>, cudaFuncAttributeMaxDynamicSharedMemorySize, GEMM_SMEM_BYTES);
        cudaFuncSetAttribute(gemm_tc<2>, cudaFuncAttributeMaxDynamicSharedMemorySize, GEMM_SMEM_BYTES);
        cudaFuncSetAttribute(gemm_tc<3>, cudaFuncAttributeMaxDynamicSharedMemorySize, GEMM_SMEM_BYTES);
        attr_done = true;
    }

    ln1_window_kernel<<<NTOK / 8, 256>>>(x, n1g, n1b, xw);

    gemm_tc<0><<<dim3(768 / TN, NTOK / TM), 256, GEMM_SMEM_BYTES>>>(
        xw, qkv_w, qkv_b, qkvb, NTOK, 768, CC, nullptr);

    attn_kernel<<<dim3(BWIN, HEADS), 256>>>(qkvb, rpb_tab, amask, sal_fg, sal_bg, obuf);

    gemm_tc<3><<<dim3(CC / TN, NTOK / TM), 256, GEMM_SMEM_BYTES>>>(
        obuf, proj_w, proj_b, x2, NTOK, CC, CC, x);

    ln2_kernel<<<NTOK / 8, 256>>>(x2, n2g, n2b, xn2);

    gemm_tc<1><<<dim3(1024 / TN, NTOK / TM), 256, GEMM_SMEM_BYTES>>>(
        xn2, fc1_w, fc1_b, h1, NTOK, 1024, CC, nullptr);

    gemm_tc<2><<<dim3(CC / TN, NTOK / TM), 256, GEMM_SMEM_BYTES>>>(
        h1, fc2_w, fc2_b, out, NTOK, CC, 1024, x2);
}

// round 5
// speedup vs baseline: 2.4857x; 1.0354x over previous
#include <cuda_runtime.h>
#include <cuda_bf16.h>
#include <math.h>
#include <cstdint>

// ---------------- problem constants ----------------
#define BB    32
#define HH    56
#define WW    56
#define CC    256
#define WIN   7
#define SHIFT 3
#define HEADS 8
#define HD    32
#define NN    49
#define NWIN  64
#define BWIN  (BB*NWIN)   // 2048
#define NTOK  (BWIN*NN)   // 100352
#define LL    (HH*WW)     // 3136

// ---------------- scratch ----------------
__device__ float g_xw  [(size_t)NTOK*CC];
__device__ float g_qkv [(size_t)NTOK*3*CC];
__device__ float g_obuf[(size_t)NTOK*CC];
__device__ float g_x2  [(size_t)BB*LL*CC];
__device__ float g_xn2 [(size_t)NTOK*CC];
__device__ float g_h1  [(size_t)NTOK*4*CC];

// ---------------- helpers ----------------
__device__ __forceinline__ float warp_sum(float v) {
#pragma unroll
    for (int o = 16; o; o >>= 1) v += __shfl_xor_sync(0xffffffffu, v, o);
    return v;
}
__device__ __forceinline__ float warp_max(float v) {
#pragma unroll
    for (int o = 16; o; o >>= 1) v = fmaxf(v, __shfl_xor_sync(0xffffffffu, v, o));
    return v;
}
__device__ __forceinline__ uint32_t smem_u32(const void* p) {
    uint32_t a;
    asm("{ .reg .u64 t; cvta.to.shared.u64 t, %1; cvt.u32.u64 %0, t; }" : "=r"(a) : "l"(p));
    return a;
}
__device__ __forceinline__ uint32_t cvt_tf32(float f) {
    uint32_t u; asm("cvt.rna.tf32.f32 %0, %1;" : "=r"(u) : "f"(f)); return u;
}
__device__ __forceinline__ int tok_to_imgrow(int tok) {
    int n  = tok % NN;
    int bw = tok / NN;
    int b  = bw >> 6;
    int w  = bw & 63;
    int hs = (w >> 3) * WIN + n / WIN;
    int ws = (w & 7)  * WIN + n % WIN;
    int h0 = hs + SHIFT; if (h0 >= HH) h0 -= HH;
    int w0 = ws + SHIFT; if (w0 >= WW) w0 -= WW;
    return b * LL + h0 * WW + w0;
}

#define CP_ASYNC16(dst, src) \
    asm volatile("cp.async.cg.shared.global [%0], [%1], 16;" :: "r"(dst), "l"(src))
#define CP_COMMIT() asm volatile("cp.async.commit_group;" ::: "memory")
#define CP_WAIT(n)  asm volatile("cp.async.wait_group %0;" :: "n"(n) : "memory")

__device__ __forceinline__ void mma_tf32(float* c, const uint32_t* a, const uint32_t* b) {
    asm volatile(
        "mma.sync.aligned.m16n8k8.row.col.f32.tf32.tf32.f32 "
        "{%0,%1,%2,%3}, {%4,%5,%6,%7}, {%8,%9}, {%0,%1,%2,%3};"
        : "+f"(c[0]), "+f"(c[1]), "+f"(c[2]), "+f"(c[3])
        : "r"(a[0]), "r"(a[1]), "r"(a[2]), "r"(a[3]), "r"(b[0]), "r"(b[1]));
}

// ---------------- LN kernels ----------------
__global__ void ln1_window_kernel(const float* __restrict__ x,
                                  const float* __restrict__ g,
                                  const float* __restrict__ b,
                                  float* __restrict__ xw) {
    int tok  = blockIdx.x * 8 + (threadIdx.x >> 5);
    int lane = threadIdx.x & 31;
    if (tok >= NTOK) return;
    const float* row = x + (size_t)tok_to_imgrow(tok) * CC;
    float vals[8], s = 0.f;
#pragma unroll
    for (int q = 0; q < 8; q++) { vals[q] = row[lane + 32 * q]; s += vals[q]; }
    float mean = warp_sum(s) * (1.f / CC);
    float vv = 0.f;
#pragma unroll
    for (int q = 0; q < 8; q++) { float d = vals[q] - mean; vv += d * d; }
    float inv = rsqrtf(warp_sum(vv) * (1.f / CC) + 1e-5f);
    float* out = xw + (size_t)tok * CC;
#pragma unroll
    for (int q = 0; q < 8; q++) {
        int c = lane + 32 * q;
        out[c] = (vals[q] - mean) * inv * g[c] + b[c];
    }
}
__global__ void ln2_kernel(const float* __restrict__ x,
                           const float* __restrict__ g,
                           const float* __restrict__ b,
                           float* __restrict__ out_) {
    int tok  = blockIdx.x * 8 + (threadIdx.x >> 5);
    int lane = threadIdx.x & 31;
    if (tok >= NTOK) return;
    const float* row = x + (size_t)tok * CC;
    float vals[8], s = 0.f;
#pragma unroll
    for (int q = 0; q < 8; q++) { vals[q] = row[lane + 32 * q]; s += vals[q]; }
    float mean = warp_sum(s) * (1.f / CC);
    float vv = 0.f;
#pragma unroll
    for (int q = 0; q < 8; q++) { float d = vals[q] - mean; vv += d * d; }
    float inv = rsqrtf(warp_sum(vv) * (1.f / CC) + 1e-5f);
    float* out = out_ + (size_t)tok * CC;
#pragma unroll
    for (int q = 0; q < 8; q++) {
        int c = lane + 32 * q;
        out[c] = (vals[q] - mean) * inv * g[c] + b[c];
    }
}

// ---------------- tf32 mma.sync GEMM: C = A @ W^T + bias ----------------
// Block tile 64x128, warp tile 32x32, 8 warps, aiming 3 CTAs/SM.
// MODE 0 plain | 1 GELU | 2 +res | 3 scatter(window-reverse)+res
#define TM 64
#define TN 128
#define TK 32
#define SPAD 36                          // padded k-stride (floats)
#define A_BYTES (TM * SPAD * 4)          // 9216
#define B_BYTES (TN * SPAD * 4)          // 18432
#define STAGE_BYTES (A_BYTES + B_BYTES)  // 27648
#define GEMM_SMEM_BYTES (2 * STAGE_BYTES)

template <int MODE>
__global__ __launch_bounds__(256, 3)
void gemm_tc(const float* __restrict__ A, const float* __restrict__ W,
             const float* __restrict__ bias, float* __restrict__ C,
             int M, int N, int K, const float* __restrict__ res) {
    extern __shared__ __align__(128) char smem[];
    uint32_t sb = smem_u32(smem);
    int tid = threadIdx.x, wid = tid >> 5, lane = tid & 31;
    int wm = wid >> 2, wn = wid & 3;          // 2 x 4 warp grid, warp tile 32x32
    int m0 = blockIdx.y * TM, n0 = blockIdx.x * TN;

    float acc[2][4][4];
#pragma unroll
    for (int i = 0; i < 2; i++)
#pragma unroll
        for (int j = 0; j < 4; j++)
#pragma unroll
            for (int r = 0; r < 4; r++) acc[i][j][r] = 0.f;

    // global->smem load mapping (float4 granularity, 8 f4 per 32-float row)
    int lrow = tid >> 3;            // 0..31
    int lc4  = tid & 7;
    const float* gA = A + (size_t)(m0 + lrow) * K + lc4 * 4;   // rows lrow, lrow+32
    const float* gW = W + (size_t)(n0 + lrow) * K + lc4 * 4;   // rows lrow .. +96
    uint32_t dA = sb + lrow * (SPAD * 4) + lc4 * 16;
    uint32_t dB = sb + A_BYTES + lrow * (SPAD * 4) + lc4 * 16;

    int KT = K / TK;
    // prologue: stage 0
#pragma unroll
    for (int p = 0; p < 2; p++)
        CP_ASYNC16(dA + p * 32 * (SPAD * 4), gA + (size_t)p * 32 * K);
#pragma unroll
    for (int p = 0; p < 4; p++)
        CP_ASYNC16(dB + p * 32 * (SPAD * 4), gW + (size_t)p * 32 * K);
    CP_COMMIT();

#pragma unroll 1
    for (int kt = 0; kt < KT; kt++) {
        bool more = (kt + 1 < KT);
        if (more) {
            uint32_t off = ((kt + 1) & 1) * STAGE_BYTES;
            const float* sA = gA + (size_t)(kt + 1) * TK;
            const float* sW = gW + (size_t)(kt + 1) * TK;
#pragma unroll
            for (int p = 0; p < 2; p++)
                CP_ASYNC16(dA + off + p * 32 * (SPAD * 4), sA + (size_t)p * 32 * K);
#pragma unroll
            for (int p = 0; p < 4; p++)
                CP_ASYNC16(dB + off + p * 32 * (SPAD * 4), sW + (size_t)p * 32 * K);
            CP_COMMIT();
            CP_WAIT(1);
        } else {
            CP_WAIT(0);
        }
        __syncthreads();

        const float* As = (const float*)(smem + (kt & 1) * STAGE_BYTES);
        const float* Bs = (const float*)(smem + (kt & 1) * STAGE_BYTES + A_BYTES);
#pragma unroll
        for (int ks = 0; ks < 4; ks++) {
            int k0 = ks * 8 + (lane & 3);
            uint32_t af[2][4], bf[4][2];
#pragma unroll
            for (int i = 0; i < 2; i++) {
                int r = wm * 32 + i * 16 + (lane >> 2);
                af[i][0] = cvt_tf32(As[r * SPAD + k0]);
                af[i][1] = cvt_tf32(As[(r + 8) * SPAD + k0]);
                af[i][2] = cvt_tf32(As[r * SPAD + k0 + 4]);
                af[i][3] = cvt_tf32(As[(r + 8) * SPAD + k0 + 4]);
            }
#pragma unroll
            for (int j = 0; j < 4; j++) {
                int c = wn * 32 + j * 8 + (lane >> 2);
                bf[j][0] = cvt_tf32(Bs[c * SPAD + k0]);
                bf[j][1] = cvt_tf32(Bs[c * SPAD + k0 + 4]);
            }
#pragma unroll
            for (int i = 0; i < 2; i++)
#pragma unroll
                for (int j = 0; j < 4; j++)
                    mma_tf32(acc[i][j], af[i], bf[j]);
        }
        __syncthreads();
    }

    // epilogue: write C fragments directly
#pragma unroll
    for (int i = 0; i < 2; i++) {
#pragma unroll
        for (int half = 0; half < 2; half++) {
            int m = m0 + wm * 32 + i * 16 + (lane >> 2) + half * 8;
            size_t rout = (size_t)m;
            if (MODE == 3) rout = (size_t)tok_to_imgrow(m);
#pragma unroll
            for (int j = 0; j < 4; j++) {
                int col = n0 + wn * 32 + j * 8 + 2 * (lane & 3);
                float v0 = acc[i][j][half * 2 + 0] + bias[col];
                float v1 = acc[i][j][half * 2 + 1] + bias[col + 1];
                if (MODE == 1) {
                    v0 = 0.5f * v0 * (1.f + erff(v0 * 0.7071067811865476f));
                    v1 = 0.5f * v1 * (1.f + erff(v1 * 0.7071067811865476f));
                }
                if (MODE == 2) {
                    v0 += res[(size_t)m * N + col];
                    v1 += res[(size_t)m * N + col + 1];
                }
                if (MODE == 3) {
                    v0 += res[rout * N + col];
                    v1 += res[rout * N + col + 1];
                }
                *(float2*)(C + rout * N + col) = make_float2(v0, v1);
            }
        }
    }
}

// ---------------- K3: windowed attention, triple softmax --------------------
#define QP 33
__global__ __launch_bounds__(256)
void attn_kernel(const float* __restrict__ qkv,
                 const float* __restrict__ rpb_table,
                 const float* __restrict__ attn_mask,
                 const float* __restrict__ sal_fg,
                 const float* __restrict__ sal_bg,
                 float* __restrict__ obuf) {
    int bw = blockIdx.x;
    int h  = blockIdx.y;
    int tid  = threadIdx.x;
    int lane = tid & 31;
    int warp = tid >> 5;

    __shared__ float qs[NN * QP];
    __shared__ float ks[NN * QP];
    __shared__ float vs[NN * QP];
    __shared__ float sc[NN * NN];
    __shared__ float rpb_s[169];
    __shared__ float fg_s[NN], bg_s[NN];

    const float* base = qkv + (size_t)bw * NN * (3 * CC);
    const float scale = 0.17677669529663687f;
    for (int t = tid; t < NN * HD; t += 256) {
        int n = t >> 5, dd = t & 31;
        qs[n * QP + dd] = base[n * 768 +          h * HD + dd] * scale;
        ks[n * QP + dd] = base[n * 768 + CC     + h * HD + dd];
        vs[n * QP + dd] = base[n * 768 + 2 * CC + h * HD + dd];
    }
    if (tid < 169) rpb_s[tid] = rpb_table[tid * HEADS + h];
    if (tid < NN) {
        fg_s[tid] = sal_fg[(size_t)bw * (NN * NN) + tid];
        bg_s[tid] = sal_bg[(size_t)bw * (NN * NN) + tid];
    }
    __syncthreads();

    int w = bw & 63;
    const float* am = attn_mask + (size_t)w * (NN * NN);
    for (int t = tid; t < NN * NN; t += 256) {
        int i = t / NN, j = t - i * NN;
        float s = 0.f;
        const float* qi = qs + i * QP;
        const float* kj = ks + j * QP;
#pragma unroll
        for (int dd = 0; dd < HD; dd++) s += qi[dd] * kj[dd];
        int dy = i / WIN - j / WIN + (WIN - 1);
        int dx = i % WIN - j % WIN + (WIN - 1);
        sc[t] = s + rpb_s[dy * (2 * WIN - 1) + dx] + am[t];
    }
    __syncthreads();

    for (int i = warp; i < NN; i += 8) {
        float* rowp = sc + i * NN;
        float a0 = rowp[lane];
        bool v1  = (lane + 32) < NN;
        float a1 = v1 ? rowp[lane + 32] : -1e30f;
        float f0 = fg_s[lane], b0m = bg_s[lane];
        float f1 = v1 ? fg_s[lane + 32] : 0.f;
        float b1m = v1 ? bg_s[lane + 32] : 0.f;

        float m1 = warp_max(fmaxf(a0, a1));
        float m2 = warp_max(fmaxf(a0 + f0, v1 ? a1 + f1 : -1e30f));
        float m3 = warp_max(fmaxf(a0 + b0m, v1 ? a1 + b1m : -1e30f));

        float e1a = __expf(a0 - m1),       e1b = v1 ? __expf(a1 - m1) : 0.f;
        float e2a = __expf(a0 + f0 - m2),  e2b = v1 ? __expf(a1 + f1 - m2) : 0.f;
        float e3a = __expf(a0 + b0m - m3), e3b = v1 ? __expf(a1 + b1m - m3) : 0.f;

        float i1 = 1.f / warp_sum(e1a + e1b);
        float i2 = 1.f / warp_sum(e2a + e2b);
        float i3 = 1.f / warp_sum(e3a + e3b);

        rowp[lane] = e1a * i1 + e2a * i2 - e3a * i3;
        if (v1) rowp[lane + 32] = e1b * i1 + e2b * i2 - e3b * i3;
    }
    __syncthreads();

    for (int t = tid; t < NN * HD; t += 256) {
        int i = t >> 5, dd = t & 31;
        const float* wrow = sc + i * NN;
        float acc = 0.f;
#pragma unroll
        for (int j = 0; j < NN; j++) acc += wrow[j] * vs[j * QP + dd];
        obuf[((size_t)bw * NN + i) * CC + h * HD + dd] = acc;
    }
}

// ---------------- launch ----------------
extern "C" void kernel_launch(void* const* d_in, const int* in_sizes, int n_in,
                              void* d_out, int out_size) {
    const float* x       = (const float*)d_in[0];
    const float* qkv_w   = (const float*)d_in[1];
    const float* qkv_b   = (const float*)d_in[2];
    const float* rpb_tab = (const float*)d_in[3];
    const float* proj_w  = (const float*)d_in[4];
    const float* proj_b  = (const float*)d_in[5];
    const float* n1g     = (const float*)d_in[6];
    const float* n1b     = (const float*)d_in[7];
    const float* n2g     = (const float*)d_in[8];
    const float* n2b     = (const float*)d_in[9];
    const float* fc1_w   = (const float*)d_in[10];
    const float* fc1_b   = (const float*)d_in[11];
    const float* fc2_w   = (const float*)d_in[12];
    const float* fc2_b   = (const float*)d_in[13];
    const float* amask   = (const float*)d_in[14];
    const float* sal_fg  = (const float*)d_in[15];
    const float* sal_bg  = (const float*)d_in[16];
    float* out = (float*)d_out;

    float *xw, *qkvb, *obuf, *x2, *xn2, *h1;
    cudaGetSymbolAddress((void**)&xw,   g_xw);
    cudaGetSymbolAddress((void**)&qkvb, g_qkv);
    cudaGetSymbolAddress((void**)&obuf, g_obuf);
    cudaGetSymbolAddress((void**)&x2,   g_x2);
    cudaGetSymbolAddress((void**)&xn2,  g_xn2);
    cudaGetSymbolAddress((void**)&h1,   g_h1);

    static bool attr_done = false;
    if (!attr_done) {
        cudaFuncSetAttribute(gemm_tc<0>, cudaFuncAttributeMaxDynamicSharedMemorySize, GEMM_SMEM_BYTES);
        cudaFuncSetAttribute(gemm_tc<1>, cudaFuncAttributeMaxDynamicSharedMemorySize, GEMM_SMEM_BYTES);
        cudaFuncSetAttribute(gemm_tc<2>, cudaFuncAttributeMaxDynamicSharedMemorySize, GEMM_SMEM_BYTES);
        cudaFuncSetAttribute(gemm_tc<3>, cudaFuncAttributeMaxDynamicSharedMemorySize, GEMM_SMEM_BYTES);
        attr_done = true;
    }

    ln1_window_kernel<<<NTOK / 8, 256>>>(x, n1g, n1b, xw);

    gemm_tc<0><<<dim3(768 / TN, NTOK / TM), 256, GEMM_SMEM_BYTES>>>(
        xw, qkv_w, qkv_b, qkvb, NTOK, 768, CC, nullptr);

    attn_kernel<<<dim3(BWIN, HEADS), 256>>>(qkvb, rpb_tab, amask, sal_fg, sal_bg, obuf);

    gemm_tc<3><<<dim3(CC / TN, NTOK / TM), 256, GEMM_SMEM_BYTES>>>(
        obuf, proj_w, proj_b, x2, NTOK, CC, CC, x);

    ln2_kernel<<<NTOK / 8, 256>>>(x2, n2g, n2b, xn2);

    gemm_tc<1><<<dim3(1024 / TN, NTOK / TM), 256, GEMM_SMEM_BYTES>>>(
        xn2, fc1_w, fc1_b, h1, NTOK, 1024, CC, nullptr);

    gemm_tc<2><<<dim3(CC / TN, NTOK / TM), 256, GEMM_SMEM_BYTES>>>(
        h1, fc2_w, fc2_b, out, NTOK, CC, 1024, x2);
}

// round 9
// speedup vs baseline: 2.5250x; 1.0158x over previous
#include <cuda_runtime.h>
#include <cuda_bf16.h>
#include <math.h>
#include <cstdint>

// ---------------- problem constants ----------------
#define BB    32
#define HH    56
#define WW    56
#define CC    256
#define WIN   7
#define SHIFT 3
#define HEADS 8
#define HD    32
#define NN    49
#define NWIN  64
#define BWIN  (BB*NWIN)   // 2048
#define NTOK  (BWIN*NN)   // 100352
#define LL    (HH*WW)     // 3136

// ---------------- scratch ----------------
__device__ float g_xw  [(size_t)NTOK*CC];
__device__ float g_qkv [(size_t)NTOK*3*CC];
__device__ float g_obuf[(size_t)NTOK*CC];
__device__ float g_x2  [(size_t)BB*LL*CC];
__device__ float g_xn2 [(size_t)NTOK*CC];
__device__ float g_h1  [(size_t)NTOK*4*CC];

// ---------------- helpers ----------------
__device__ __forceinline__ float warp_sum(float v) {
#pragma unroll
    for (int o = 16; o; o >>= 1) v += __shfl_xor_sync(0xffffffffu, v, o);
    return v;
}
__device__ __forceinline__ float warp_max(float v) {
#pragma unroll
    for (int o = 16; o; o >>= 1) v = fmaxf(v, __shfl_xor_sync(0xffffffffu, v, o));
    return v;
}
__device__ __forceinline__ uint32_t smem_u32(const void* p) {
    uint32_t a;
    asm("{ .reg .u64 t; cvta.to.shared.u64 t, %1; cvt.u32.u64 %0, t; }" : "=r"(a) : "l"(p));
    return a;
}
__device__ __forceinline__ int tok_to_imgrow(int tok) {
    int n  = tok % NN;
    int bw = tok / NN;
    int b  = bw >> 6;
    int w  = bw & 63;
    int hs = (w >> 3) * WIN + n / WIN;
    int ws = (w & 7)  * WIN + n % WIN;
    int h0 = hs + SHIFT; if (h0 >= HH) h0 -= HH;
    int w0 = ws + SHIFT; if (w0 >= WW) w0 -= WW;
    return b * LL + h0 * WW + w0;
}

#define CP_ASYNC16(dst, src) \
    asm volatile("cp.async.cg.shared.global [%0], [%1], 16;" :: "r"(dst), "l"(src))
#define CP_COMMIT() asm volatile("cp.async.commit_group;" ::: "memory")
#define CP_WAIT(n)  asm volatile("cp.async.wait_group %0;" :: "n"(n) : "memory")

// raw fp32 bits fed to tf32 MMA: HW reads only the tf32 field (truncation).
__device__ __forceinline__ void mma_tf32(float* c, const uint32_t* a, const uint32_t* b) {
    asm volatile(
        "mma.sync.aligned.m16n8k8.row.col.f32.tf32.tf32.f32 "
        "{%0,%1,%2,%3}, {%4,%5,%6,%7}, {%8,%9}, {%0,%1,%2,%3};"
        : "+f"(c[0]), "+f"(c[1]), "+f"(c[2]), "+f"(c[3])
        : "r"(a[0]), "r"(a[1]), "r"(a[2]), "r"(a[3]), "r"(b[0]), "r"(b[1]));
}

// ---------------- LN kernels ----------------
__global__ void ln1_window_kernel(const float* __restrict__ x,
                                  const float* __restrict__ g,
                                  const float* __restrict__ b,
                                  float* __restrict__ xw) {
    int tok  = blockIdx.x * 8 + (threadIdx.x >> 5);
    int lane = threadIdx.x & 31;
    if (tok >= NTOK) return;
    const float* row = x + (size_t)tok_to_imgrow(tok) * CC;
    float vals[8], s = 0.f;
#pragma unroll
    for (int q = 0; q < 8; q++) { vals[q] = row[lane + 32 * q]; s += vals[q]; }
    float mean = warp_sum(s) * (1.f / CC);
    float vv = 0.f;
#pragma unroll
    for (int q = 0; q < 8; q++) { float d = vals[q] - mean; vv += d * d; }
    float inv = rsqrtf(warp_sum(vv) * (1.f / CC) + 1e-5f);
    float* out = xw + (size_t)tok * CC;
#pragma unroll
    for (int q = 0; q < 8; q++) {
        int c = lane + 32 * q;
        out[c] = (vals[q] - mean) * inv * g[c] + b[c];
    }
}
__global__ void ln2_kernel(const float* __restrict__ x,
                           const float* __restrict__ g,
                           const float* __restrict__ b,
                           float* __restrict__ out_) {
    int tok  = blockIdx.x * 8 + (threadIdx.x >> 5);
    int lane = threadIdx.x & 31;
    if (tok >= NTOK) return;
    const float* row = x + (size_t)tok * CC;
    float vals[8], s = 0.f;
#pragma unroll
    for (int q = 0; q < 8; q++) { vals[q] = row[lane + 32 * q]; s += vals[q]; }
    float mean = warp_sum(s) * (1.f / CC);
    float vv = 0.f;
#pragma unroll
    for (int q = 0; q < 8; q++) { float d = vals[q] - mean; vv += d * d; }
    float inv = rsqrtf(warp_sum(vv) * (1.f / CC) + 1e-5f);
    float* out = out_ + (size_t)tok * CC;
#pragma unroll
    for (int q = 0; q < 8; q++) {
        int c = lane + 32 * q;
        out[c] = (vals[q] - mean) * inv * g[c] + b[c];
    }
}

// ---------------- tf32 mma.sync GEMM: C = A @ W^T + bias ----------------
// Block tile 64x128, warp tile 32x32, 8 warps, 3 CTAs/SM.
// MODE 0 plain | 1 GELU | 2 +res | 3 scatter(window-reverse)+res
#define TM 64
#define TN 128
#define TK 32
#define SPAD 36                          // padded k-stride (floats)
#define A_BYTES (TM * SPAD * 4)          // 9216
#define B_BYTES (TN * SPAD * 4)          // 18432
#define STAGE_BYTES (A_BYTES + B_BYTES)  // 27648
#define GEMM_SMEM_BYTES (2 * STAGE_BYTES)

template <int MODE>
__global__ __launch_bounds__(256, 3)
void gemm_tc(const float* __restrict__ A, const float* __restrict__ W,
             const float* __restrict__ bias, float* __restrict__ C,
             int M, int N, int K, const float* __restrict__ res) {
    extern __shared__ __align__(128) char smem[];
    uint32_t sb = smem_u32(smem);
    int tid = threadIdx.x, wid = tid >> 5, lane = tid & 31;
    int wm = wid >> 2, wn = wid & 3;          // 2 x 4 warp grid, warp tile 32x32
    int m0 = blockIdx.y * TM, n0 = blockIdx.x * TN;

    float acc[2][4][4];
#pragma unroll
    for (int i = 0; i < 2; i++)
#pragma unroll
        for (int j = 0; j < 4; j++)
#pragma unroll
            for (int r = 0; r < 4; r++) acc[i][j][r] = 0.f;

    // global->smem load mapping
    int lrow = tid >> 3;            // 0..31
    int lc4  = tid & 7;
    const float* gA = A + (size_t)(m0 + lrow) * K + lc4 * 4;
    const float* gW = W + (size_t)(n0 + lrow) * K + lc4 * 4;
    uint32_t dA = sb + lrow * (SPAD * 4) + lc4 * 16;
    uint32_t dB = sb + A_BYTES + lrow * (SPAD * 4) + lc4 * 16;

    int KT = K / TK;
#pragma unroll
    for (int p = 0; p < 2; p++)
        CP_ASYNC16(dA + p * 32 * (SPAD * 4), gA + (size_t)p * 32 * K);
#pragma unroll
    for (int p = 0; p < 4; p++)
        CP_ASYNC16(dB + p * 32 * (SPAD * 4), gW + (size_t)p * 32 * K);
    CP_COMMIT();

#pragma unroll 1
    for (int kt = 0; kt < KT; kt++) {
        bool more = (kt + 1 < KT);
        if (more) {
            uint32_t off = ((kt + 1) & 1) * STAGE_BYTES;
            const float* sA = gA + (size_t)(kt + 1) * TK;
            const float* sW = gW + (size_t)(kt + 1) * TK;
#pragma unroll
            for (int p = 0; p < 2; p++)
                CP_ASYNC16(dA + off + p * 32 * (SPAD * 4), sA + (size_t)p * 32 * K);
#pragma unroll
            for (int p = 0; p < 4; p++)
                CP_ASYNC16(dB + off + p * 32 * (SPAD * 4), sW + (size_t)p * 32 * K);
            CP_COMMIT();
            CP_WAIT(1);
        } else {
            CP_WAIT(0);
        }
        __syncthreads();

        const uint32_t* As = (const uint32_t*)(smem + (kt & 1) * STAGE_BYTES);
        const uint32_t* Bs = (const uint32_t*)(smem + (kt & 1) * STAGE_BYTES + A_BYTES);
#pragma unroll
        for (int ks = 0; ks < 4; ks++) {
            int k0 = ks * 8 + (lane & 3);
            uint32_t af[2][4], bf[4][2];
#pragma unroll
            for (int i = 0; i < 2; i++) {
                int r = wm * 32 + i * 16 + (lane >> 2);
                af[i][0] = As[r * SPAD + k0];
                af[i][1] = As[(r + 8) * SPAD + k0];
                af[i][2] = As[r * SPAD + k0 + 4];
                af[i][3] = As[(r + 8) * SPAD + k0 + 4];
            }
#pragma unroll
            for (int j = 0; j < 4; j++) {
                int c = wn * 32 + j * 8 + (lane >> 2);
                bf[j][0] = Bs[c * SPAD + k0];
                bf[j][1] = Bs[c * SPAD + k0 + 4];
            }
#pragma unroll
            for (int i = 0; i < 2; i++)
#pragma unroll
                for (int j = 0; j < 4; j++)
                    mma_tf32(acc[i][j], af[i], bf[j]);
        }
        __syncthreads();
    }

    // epilogue
#pragma unroll
    for (int i = 0; i < 2; i++) {
#pragma unroll
        for (int half = 0; half < 2; half++) {
            int m = m0 + wm * 32 + i * 16 + (lane >> 2) + half * 8;
            size_t rout = (size_t)m;
            if (MODE == 3) rout = (size_t)tok_to_imgrow(m);
#pragma unroll
            for (int j = 0; j < 4; j++) {
                int col = n0 + wn * 32 + j * 8 + 2 * (lane & 3);
                float v0 = acc[i][j][half * 2 + 0] + bias[col];
                float v1 = acc[i][j][half * 2 + 1] + bias[col + 1];
                if (MODE == 1) {
                    v0 = 0.5f * v0 * (1.f + erff(v0 * 0.7071067811865476f));
                    v1 = 0.5f * v1 * (1.f + erff(v1 * 0.7071067811865476f));
                }
                if (MODE == 2) {
                    v0 += res[(size_t)m * N + col];
                    v1 += res[(size_t)m * N + col + 1];
                }
                if (MODE == 3) {
                    v0 += res[rout * N + col];
                    v1 += res[rout * N + col + 1];
                }
                *(float2*)(C + rout * N + col) = make_float2(v0, v1);
            }
        }
    }
}

// ---------------- K3: windowed attention, triple softmax --------------------
#define QP 33
__global__ __launch_bounds__(256)
void attn_kernel(const float* __restrict__ qkv,
                 const float* __restrict__ rpb_table,
                 const float* __restrict__ attn_mask,
                 const float* __restrict__ sal_fg,
                 const float* __restrict__ sal_bg,
                 float* __restrict__ obuf) {
    int bw = blockIdx.x;
    int h  = blockIdx.y;
    int tid  = threadIdx.x;
    int lane = tid & 31;
    int warp = tid >> 5;

    __shared__ float qs[NN * QP];
    __shared__ float ks[NN * QP];
    __shared__ float vs[NN * QP];
    __shared__ float sc[NN * NN];
    __shared__ float rpb_s[169];
    __shared__ float fg_s[NN], bg_s[NN];

    const float* base = qkv + (size_t)bw * NN * (3 * CC);
    const float scale = 0.17677669529663687f;
    for (int t = tid; t < NN * HD; t += 256) {
        int n = t >> 5, dd = t & 31;
        qs[n * QP + dd] = base[n * 768 +          h * HD + dd] * scale;
        ks[n * QP + dd] = base[n * 768 + CC     + h * HD + dd];
        vs[n * QP + dd] = base[n * 768 + 2 * CC + h * HD + dd];
    }
    if (tid < 169) rpb_s[tid] = rpb_table[tid * HEADS + h];
    if (tid < NN) {
        fg_s[tid] = sal_fg[(size_t)bw * (NN * NN) + tid];
        bg_s[tid] = sal_bg[(size_t)bw * (NN * NN) + tid];
    }
    __syncthreads();

    int w = bw & 63;
    const float* am = attn_mask + (size_t)w * (NN * NN);
    for (int t = tid; t < NN * NN; t += 256) {
        int i = t / NN, j = t - i * NN;
        float s = 0.f;
        const float* qi = qs + i * QP;
        const float* kj = ks + j * QP;
#pragma unroll
        for (int dd = 0; dd < HD; dd++) s += qi[dd] * kj[dd];
        int dy = i / WIN - j / WIN + (WIN - 1);
        int dx = i % WIN - j % WIN + (WIN - 1);
        sc[t] = s + rpb_s[dy * (2 * WIN - 1) + dx] + am[t];
    }
    __syncthreads();

    for (int i = warp; i < NN; i += 8) {
        float* rowp = sc + i * NN;
        float a0 = rowp[lane];
        bool v1  = (lane + 32) < NN;
        float a1 = v1 ? rowp[lane + 32] : -1e30f;
        float f0 = fg_s[lane], b0m = bg_s[lane];
        float f1 = v1 ? fg_s[lane + 32] : 0.f;
        float b1m = v1 ? bg_s[lane + 32] : 0.f;

        float m1 = warp_max(fmaxf(a0, a1));
        float m2 = warp_max(fmaxf(a0 + f0, v1 ? a1 + f1 : -1e30f));
        float m3 = warp_max(fmaxf(a0 + b0m, v1 ? a1 + b1m : -1e30f));

        float e1a = __expf(a0 - m1),       e1b = v1 ? __expf(a1 - m1) : 0.f;
        float e2a = __expf(a0 + f0 - m2),  e2b = v1 ? __expf(a1 + f1 - m2) : 0.f;
        float e3a = __expf(a0 + b0m - m3), e3b = v1 ? __expf(a1 + b1m - m3) : 0.f;

        float i1 = 1.f / warp_sum(e1a + e1b);
        float i2 = 1.f / warp_sum(e2a + e2b);
        float i3 = 1.f / warp_sum(e3a + e3b);

        rowp[lane] = e1a * i1 + e2a * i2 - e3a * i3;
        if (v1) rowp[lane + 32] = e1b * i1 + e2b * i2 - e3b * i3;
    }
    __syncthreads();

    for (int t = tid; t < NN * HD; t += 256) {
        int i = t >> 5, dd = t & 31;
        const float* wrow = sc + i * NN;
        float acc = 0.f;
#pragma unroll
        for (int j = 0; j < NN; j++) acc += wrow[j] * vs[j * QP + dd];
        obuf[((size_t)bw * NN + i) * CC + h * HD + dd] = acc;
    }
}

// ---------------- launch ----------------
extern "C" void kernel_launch(void* const* d_in, const int* in_sizes, int n_in,
                              void* d_out, int out_size) {
    const float* x       = (const float*)d_in[0];
    const float* qkv_w   = (const float*)d_in[1];
    const float* qkv_b   = (const float*)d_in[2];
    const float* rpb_tab = (const float*)d_in[3];
    const float* proj_w  = (const float*)d_in[4];
    const float* proj_b  = (const float*)d_in[5];
    const float* n1g     = (const float*)d_in[6];
    const float* n1b     = (const float*)d_in[7];
    const float* n2g     = (const float*)d_in[8];
    const float* n2b     = (const float*)d_in[9];
    const float* fc1_w   = (const float*)d_in[10];
    const float* fc1_b   = (const float*)d_in[11];
    const float* fc2_w   = (const float*)d_in[12];
    const float* fc2_b   = (const float*)d_in[13];
    const float* amask   = (const float*)d_in[14];
    const float* sal_fg  = (const float*)d_in[15];
    const float* sal_bg  = (const float*)d_in[16];
    float* out = (float*)d_out;

    float *xw, *qkvb, *obuf, *x2, *xn2, *h1;
    cudaGetSymbolAddress((void**)&xw,   g_xw);
    cudaGetSymbolAddress((void**)&qkvb, g_qkv);
    cudaGetSymbolAddress((void**)&obuf, g_obuf);
    cudaGetSymbolAddress((void**)&x2,   g_x2);
    cudaGetSymbolAddress((void**)&xn2,  g_xn2);
    cudaGetSymbolAddress((void**)&h1,   g_h1);

    static bool attr_done = false;
    if (!attr_done) {
        cudaFuncSetAttribute(gemm_tc<0>, cudaFuncAttributeMaxDynamicSharedMemorySize, GEMM_SMEM_BYTES);
        cudaFuncSetAttribute(gemm_tc<1>, cudaFuncAttributeMaxDynamicSharedMemorySize, GEMM_SMEM_BYTES);
        cudaFuncSetAttribute(gemm_tc<2>, cudaFuncAttributeMaxDynamicSharedMemorySize, GEMM_SMEM_BYTES);
        cudaFuncSetAttribute(gemm_tc<3>, cudaFuncAttributeMaxDynamicSharedMemorySize, GEMM_SMEM_BYTES);
        attr_done = true;
    }

    ln1_window_kernel<<<NTOK / 8, 256>>>(x, n1g, n1b, xw);

    gemm_tc<0><<<dim3(768 / TN, NTOK / TM), 256, GEMM_SMEM_BYTES>>>(
        xw, qkv_w, qkv_b, qkvb, NTOK, 768, CC, nullptr);

    attn_kernel<<<dim3(BWIN, HEADS), 256>>>(qkvb, rpb_tab, amask, sal_fg, sal_bg, obuf);

    gemm_tc<3><<<dim3(CC / TN, NTOK / TM), 256, GEMM_SMEM_BYTES>>>(
        obuf, proj_w, proj_b, x2, NTOK, CC, CC, x);

    ln2_kernel<<<NTOK / 8, 256>>>(x2, n2g, n2b, xn2);

    gemm_tc<1><<<dim3(1024 / TN, NTOK / TM), 256, GEMM_SMEM_BYTES>>>(
        xn2, fc1_w, fc1_b, h1, NTOK, 1024, CC, nullptr);

    gemm_tc<2><<<dim3(CC / TN, NTOK / TM), 256, GEMM_SMEM_BYTES>>>(
        h1, fc2_w, fc2_b, out, NTOK, CC, 1024, x2);
}

// round 13
// speedup vs baseline: 3.1899x; 1.2633x over previous
#include <cuda_runtime.h>
#include <cuda_fp16.h>
#include <math.h>
#include <cstdint>

// ---------------- problem constants ----------------
#define BB    32
#define HH    56
#define WW    56
#define CC    256
#define WIN   7
#define SHIFT 3
#define HEADS 8
#define HD    32
#define NN    49
#define NWIN  64
#define BWIN  (BB*NWIN)   // 2048
#define NTOK  (BWIN*NN)   // 100352
#define LL    (HH*WW)     // 3136

// ---------------- scratch ----------------
__device__ __half g_xwh [(size_t)NTOK*CC];       // LN1 out (fp16)
__device__ float  g_qkv [(size_t)NTOK*3*CC];     // qkv gemm out (fp32, attention reads)
__device__ __half g_obufh[(size_t)NTOK*CC];      // attention out (fp16)
__device__ float  g_x2  [(size_t)BB*LL*CC];      // residual stream (fp32)
__device__ __half g_xn2h[(size_t)NTOK*CC];       // LN2 out (fp16)
__device__ __half g_h1h [(size_t)NTOK*4*CC];     // fc1+gelu out (fp16)
// fp16 weights (converted once per launch)
__device__ __half g_wqkv[768*256];
__device__ __half g_wproj[256*256];
__device__ __half g_wfc1[1024*256];
__device__ __half g_wfc2[256*1024];

// ---------------- helpers ----------------
__device__ __forceinline__ float warp_sum(float v) {
#pragma unroll
    for (int o = 16; o; o >>= 1) v += __shfl_xor_sync(0xffffffffu, v, o);
    return v;
}
__device__ __forceinline__ float warp_max(float v) {
#pragma unroll
    for (int o = 16; o; o >>= 1) v = fmaxf(v, __shfl_xor_sync(0xffffffffu, v, o));
    return v;
}
__device__ __forceinline__ uint32_t smem_u32(const void* p) {
    uint32_t a;
    asm("{ .reg .u64 t; cvta.to.shared.u64 t, %1; cvt.u32.u64 %0, t; }" : "=r"(a) : "l"(p));
    return a;
}
__device__ __forceinline__ int tok_to_imgrow(int tok) {
    int n  = tok % NN;
    int bw = tok / NN;
    int b  = bw >> 6;
    int w  = bw & 63;
    int hs = (w >> 3) * WIN + n / WIN;
    int ws = (w & 7)  * WIN + n % WIN;
    int h0 = hs + SHIFT; if (h0 >= HH) h0 -= HH;
    int w0 = ws + SHIFT; if (w0 >= WW) w0 -= WW;
    return b * LL + h0 * WW + w0;
}

#define CP_ASYNC16(dst, src) \
    asm volatile("cp.async.cg.shared.global [%0], [%1], 16;" :: "r"(dst), "l"(src))
#define CP_COMMIT() asm volatile("cp.async.commit_group;" ::: "memory")
#define CP_WAIT(n)  asm volatile("cp.async.wait_group %0;" :: "n"(n) : "memory")

__device__ __forceinline__ void mma_f16(float* c, const uint32_t* a, const uint32_t* b) {
    asm volatile(
        "mma.sync.aligned.m16n8k16.row.col.f32.f16.f16.f32 "
        "{%0,%1,%2,%3}, {%4,%5,%6,%7}, {%8,%9}, {%0,%1,%2,%3};"
        : "+f"(c[0]), "+f"(c[1]), "+f"(c[2]), "+f"(c[3])
        : "r"(a[0]), "r"(a[1]), "r"(a[2]), "r"(a[3]), "r"(b[0]), "r"(b[1]));
}

// ---------------- weight conversion (float -> half), vectorized ----------------
__global__ void cvt_f2h(const float* __restrict__ in, __half* __restrict__ out, int n4) {
    int i = blockIdx.x * 256 + threadIdx.x;
    if (i >= n4) return;
    float4 v = ((const float4*)in)[i];
    __half2* o = (__half2*)(out + (size_t)i * 4);
    o[0] = __floats2half2_rn(v.x, v.y);
    o[1] = __floats2half2_rn(v.z, v.w);
}

// ---------------- LN kernels (fp32 in -> fp16 out) ----------------
__global__ void ln1_window_kernel(const float* __restrict__ x,
                                  const float* __restrict__ g,
                                  const float* __restrict__ b,
                                  __half* __restrict__ xw) {
    int tok  = blockIdx.x * 8 + (threadIdx.x >> 5);
    int lane = threadIdx.x & 31;
    if (tok >= NTOK) return;
    const float* row = x + (size_t)tok_to_imgrow(tok) * CC;
    float vals[8], s = 0.f;
#pragma unroll
    for (int q = 0; q < 8; q++) { vals[q] = row[lane + 32 * q]; s += vals[q]; }
    float mean = warp_sum(s) * (1.f / CC);
    float vv = 0.f;
#pragma unroll
    for (int q = 0; q < 8; q++) { float d = vals[q] - mean; vv += d * d; }
    float inv = rsqrtf(warp_sum(vv) * (1.f / CC) + 1e-5f);
    __half* out = xw + (size_t)tok * CC;
#pragma unroll
    for (int q = 0; q < 8; q++) {
        int c = lane + 32 * q;
        out[c] = __float2half_rn((vals[q] - mean) * inv * g[c] + b[c]);
    }
}
__global__ void ln2_kernel(const float* __restrict__ x,
                           const float* __restrict__ g,
                           const float* __restrict__ b,
                           __half* __restrict__ out_) {
    int tok  = blockIdx.x * 8 + (threadIdx.x >> 5);
    int lane = threadIdx.x & 31;
    if (tok >= NTOK) return;
    const float* row = x + (size_t)tok * CC;
    float vals[8], s = 0.f;
#pragma unroll
    for (int q = 0; q < 8; q++) { vals[q] = row[lane + 32 * q]; s += vals[q]; }
    float mean = warp_sum(s) * (1.f / CC);
    float vv = 0.f;
#pragma unroll
    for (int q = 0; q < 8; q++) { float d = vals[q] - mean; vv += d * d; }
    float inv = rsqrtf(warp_sum(vv) * (1.f / CC) + 1e-5f);
    __half* out = out_ + (size_t)tok * CC;
#pragma unroll
    for (int q = 0; q < 8; q++) {
        int c = lane + 32 * q;
        out[c] = __float2half_rn((vals[q] - mean) * inv * g[c] + b[c]);
    }
}

// ---------------- fp16 m16n8k16 GEMM: C = A @ W^T + bias ----------------
// Block tile 64x128, warp tile 32x32, 8 warps, 3 CTAs/SM.
// MODE 0 plain->f32 | 1 GELU->f16 | 2 +res->f32 | 3 scatter+res->f32
#define TM 64
#define TN 128
#define TK 32
#define SPADH 40                          // padded k-stride (halves), 80 bytes/row
#define ROWB  80
#define A_BYTES (TM * ROWB)               // 5120
#define B_BYTES (TN * ROWB)               // 10240
#define STAGE_BYTES (A_BYTES + B_BYTES)   // 15360
#define GEMM_SMEM_BYTES (2 * STAGE_BYTES) // 30720

template <int MODE>
__global__ __launch_bounds__(256, 3)
void gemm_f16k(const __half* __restrict__ A, const __half* __restrict__ W,
               const float* __restrict__ bias, void* __restrict__ Cv,
               int M, int N, int K, const float* __restrict__ res) {
    extern __shared__ __align__(128) char smem[];
    uint32_t sb = smem_u32(smem);
    int tid = threadIdx.x, wid = tid >> 5, lane = tid & 31;
    int wm = wid >> 2, wn = wid & 3;          // 2 x 4 warp grid, warp tile 32x32
    int m0 = blockIdx.y * TM, n0 = blockIdx.x * TN;
    int g  = lane >> 2, p = lane & 3;

    float acc[2][4][4];
#pragma unroll
    for (int i = 0; i < 2; i++)
#pragma unroll
        for (int j = 0; j < 4; j++)
#pragma unroll
            for (int r = 0; r < 4; r++) acc[i][j][r] = 0.f;

    // cp.async mapping: 16B chunks, 4 per 32-half row
    int lrow = tid >> 2;            // 0..63
    int lchk = tid & 3;
    const __half* gA = A + (size_t)(m0 + lrow) * K + lchk * 8;
    const __half* gW = W + (size_t)(n0 + lrow) * K + lchk * 8;        // rows lrow, lrow+64
    uint32_t dA = sb + lrow * ROWB + lchk * 16;
    uint32_t dB = sb + A_BYTES + lrow * ROWB + lchk * 16;

    int KT = K / TK;
    CP_ASYNC16(dA, gA);
#pragma unroll
    for (int q = 0; q < 2; q++)
        CP_ASYNC16(dB + q * 64 * ROWB, gW + (size_t)q * 64 * K);
    CP_COMMIT();

#pragma unroll 1
    for (int kt = 0; kt < KT; kt++) {
        bool more = (kt + 1 < KT);
        if (more) {
            uint32_t off = ((kt + 1) & 1) * STAGE_BYTES;
            const __half* sA = gA + (size_t)(kt + 1) * TK;
            const __half* sW = gW + (size_t)(kt + 1) * TK;
            CP_ASYNC16(dA + off, sA);
#pragma unroll
            for (int q = 0; q < 2; q++)
                CP_ASYNC16(dB + off + q * 64 * ROWB, sW + (size_t)q * 64 * K);
            CP_COMMIT();
            CP_WAIT(1);
        } else {
            CP_WAIT(0);
        }
        __syncthreads();

        const uint32_t* As = (const uint32_t*)(smem + (kt & 1) * STAGE_BYTES);
        const uint32_t* Bs = (const uint32_t*)(smem + (kt & 1) * STAGE_BYTES + A_BYTES);
#pragma unroll
        for (int ks = 0; ks < 2; ks++) {
            int kb = ks * 8 + p;
            uint32_t af[2][4], bf[4][2];
#pragma unroll
            for (int i = 0; i < 2; i++) {
                int r = wm * 32 + i * 16 + g;
                af[i][0] = As[r * 20 + kb];
                af[i][1] = As[(r + 8) * 20 + kb];
                af[i][2] = As[r * 20 + kb + 4];
                af[i][3] = As[(r + 8) * 20 + kb + 4];
            }
#pragma unroll
            for (int j = 0; j < 4; j++) {
                int c = wn * 32 + j * 8 + g;
                bf[j][0] = Bs[c * 20 + kb];
                bf[j][1] = Bs[c * 20 + kb + 4];
            }
#pragma unroll
            for (int i = 0; i < 2; i++)
#pragma unroll
                for (int j = 0; j < 4; j++)
                    mma_f16(acc[i][j], af[i], bf[j]);
        }
        __syncthreads();
    }

    // epilogue
#pragma unroll
    for (int i = 0; i < 2; i++) {
#pragma unroll
        for (int half_ = 0; half_ < 2; half_++) {
            int m = m0 + wm * 32 + i * 16 + g + half_ * 8;
            size_t rout = (size_t)m;
            if (MODE == 3) rout = (size_t)tok_to_imgrow(m);
#pragma unroll
            for (int j = 0; j < 4; j++) {
                int col = n0 + wn * 32 + j * 8 + 2 * p;
                float v0 = acc[i][j][half_ * 2 + 0] + bias[col];
                float v1 = acc[i][j][half_ * 2 + 1] + bias[col + 1];
                if (MODE == 1) {
                    v0 = 0.5f * v0 * (1.f + erff(v0 * 0.7071067811865476f));
                    v1 = 0.5f * v1 * (1.f + erff(v1 * 0.7071067811865476f));
                    *(__half2*)((__half*)Cv + rout * N + col) = __floats2half2_rn(v0, v1);
                } else {
                    if (MODE == 2) {
                        v0 += res[(size_t)m * N + col];
                        v1 += res[(size_t)m * N + col + 1];
                    }
                    if (MODE == 3) {
                        v0 += res[rout * N + col];
                        v1 += res[rout * N + col + 1];
                    }
                    *(float2*)((float*)Cv + rout * N + col) = make_float2(v0, v1);
                }
            }
        }
    }
}

// ---------------- K3: windowed attention, triple softmax --------------------
#define QP 33
__global__ __launch_bounds__(256)
void attn_kernel(const float* __restrict__ qkv,
                 const float* __restrict__ rpb_table,
                 const float* __restrict__ attn_mask,
                 const float* __restrict__ sal_fg,
                 const float* __restrict__ sal_bg,
                 __half* __restrict__ obuf) {
    int bw = blockIdx.x;
    int h  = blockIdx.y;
    int tid  = threadIdx.x;
    int lane = tid & 31;
    int warp = tid >> 5;

    __shared__ float qs[NN * QP];
    __shared__ float ks[NN * QP];
    __shared__ float vs[NN * QP];
    __shared__ float sc[NN * NN];
    __shared__ float rpb_s[169];
    __shared__ float fg_s[NN], bg_s[NN];

    const float* base = qkv + (size_t)bw * NN * (3 * CC);
    const float scale = 0.17677669529663687f;
    for (int t = tid; t < NN * HD; t += 256) {
        int n = t >> 5, dd = t & 31;
        qs[n * QP + dd] = base[n * 768 +          h * HD + dd] * scale;
        ks[n * QP + dd] = base[n * 768 + CC     + h * HD + dd];
        vs[n * QP + dd] = base[n * 768 + 2 * CC + h * HD + dd];
    }
    if (tid < 169) rpb_s[tid] = rpb_table[tid * HEADS + h];
    if (tid < NN) {
        fg_s[tid] = sal_fg[(size_t)bw * (NN * NN) + tid];
        bg_s[tid] = sal_bg[(size_t)bw * (NN * NN) + tid];
    }
    __syncthreads();

    int w = bw & 63;
    const float* am = attn_mask + (size_t)w * (NN * NN);
    for (int t = tid; t < NN * NN; t += 256) {
        int i = t / NN, j = t - i * NN;
        float s = 0.f;
        const float* qi = qs + i * QP;
        const float* kj = ks + j * QP;
#pragma unroll
        for (int dd = 0; dd < HD; dd++) s += qi[dd] * kj[dd];
        int dy = i / WIN - j / WIN + (WIN - 1);
        int dx = i % WIN - j % WIN + (WIN - 1);
        sc[t] = s + rpb_s[dy * (2 * WIN - 1) + dx] + am[t];
    }
    __syncthreads();

    for (int i = warp; i < NN; i += 8) {
        float* rowp = sc + i * NN;
        float a0 = rowp[lane];
        bool v1  = (lane + 32) < NN;
        float a1 = v1 ? rowp[lane + 32] : -1e30f;
        float f0 = fg_s[lane], b0m = bg_s[lane];
        float f1 = v1 ? fg_s[lane + 32] : 0.f;
        float b1m = v1 ? bg_s[lane + 32] : 0.f;

        float m1 = warp_max(fmaxf(a0, a1));
        float m2 = warp_max(fmaxf(a0 + f0, v1 ? a1 + f1 : -1e30f));
        float m3 = warp_max(fmaxf(a0 + b0m, v1 ? a1 + b1m : -1e30f));

        float e1a = __expf(a0 - m1),       e1b = v1 ? __expf(a1 - m1) : 0.f;
        float e2a = __expf(a0 + f0 - m2),  e2b = v1 ? __expf(a1 + f1 - m2) : 0.f;
        float e3a = __expf(a0 + b0m - m3), e3b = v1 ? __expf(a1 + b1m - m3) : 0.f;

        float i1 = 1.f / warp_sum(e1a + e1b);
        float i2 = 1.f / warp_sum(e2a + e2b);
        float i3 = 1.f / warp_sum(e3a + e3b);

        rowp[lane] = e1a * i1 + e2a * i2 - e3a * i3;
        if (v1) rowp[lane + 32] = e1b * i1 + e2b * i2 - e3b * i3;
    }
    __syncthreads();

    for (int t = tid; t < NN * HD; t += 256) {
        int i = t >> 5, dd = t & 31;
        const float* wrow = sc + i * NN;
        float acc = 0.f;
#pragma unroll
        for (int j = 0; j < NN; j++) acc += wrow[j] * vs[j * QP + dd];
        obuf[((size_t)bw * NN + i) * CC + h * HD + dd] = __float2half_rn(acc);
    }
}

// ---------------- launch ----------------
extern "C" void kernel_launch(void* const* d_in, const int* in_sizes, int n_in,
                              void* d_out, int out_size) {
    const float* x       = (const float*)d_in[0];
    const float* qkv_w   = (const float*)d_in[1];
    const float* qkv_b   = (const float*)d_in[2];
    const float* rpb_tab = (const float*)d_in[3];
    const float* proj_w  = (const float*)d_in[4];
    const float* proj_b  = (const float*)d_in[5];
    const float* n1g     = (const float*)d_in[6];
    const float* n1b     = (const float*)d_in[7];
    const float* n2g     = (const float*)d_in[8];
    const float* n2b     = (const float*)d_in[9];
    const float* fc1_w   = (const float*)d_in[10];
    const float* fc1_b   = (const float*)d_in[11];
    const float* fc2_w   = (const float*)d_in[12];
    const float* fc2_b   = (const float*)d_in[13];
    const float* amask   = (const float*)d_in[14];
    const float* sal_fg  = (const float*)d_in[15];
    const float* sal_bg  = (const float*)d_in[16];
    float* out = (float*)d_out;

    __half *xwh, *obufh, *xn2h, *h1h, *wqkv, *wproj, *wfc1, *wfc2;
    float *qkvb, *x2;
    cudaGetSymbolAddress((void**)&xwh,   g_xwh);
    cudaGetSymbolAddress((void**)&qkvb,  g_qkv);
    cudaGetSymbolAddress((void**)&obufh, g_obufh);
    cudaGetSymbolAddress((void**)&x2,    g_x2);
    cudaGetSymbolAddress((void**)&xn2h,  g_xn2h);
    cudaGetSymbolAddress((void**)&h1h,   g_h1h);
    cudaGetSymbolAddress((void**)&wqkv,  g_wqkv);
    cudaGetSymbolAddress((void**)&wproj, g_wproj);
    cudaGetSymbolAddress((void**)&wfc1,  g_wfc1);
    cudaGetSymbolAddress((void**)&wfc2,  g_wfc2);

    static bool attr_done = false;
    if (!attr_done) {
        cudaFuncSetAttribute(gemm_f16k<0>, cudaFuncAttributeMaxDynamicSharedMemorySize, GEMM_SMEM_BYTES);
        cudaFuncSetAttribute(gemm_f16k<1>, cudaFuncAttributeMaxDynamicSharedMemorySize, GEMM_SMEM_BYTES);
        cudaFuncSetAttribute(gemm_f16k<2>, cudaFuncAttributeMaxDynamicSharedMemorySize, GEMM_SMEM_BYTES);
        cudaFuncSetAttribute(gemm_f16k<3>, cudaFuncAttributeMaxDynamicSharedMemorySize, GEMM_SMEM_BYTES);
        attr_done = true;
    }

    // weight conversion (runs every replay; tiny)
    cvt_f2h<<<(768 * 256 / 4 + 255) / 256, 256>>>(qkv_w, wqkv, 768 * 256 / 4);
    cvt_f2h<<<(256 * 256 / 4 + 255) / 256, 256>>>(proj_w, wproj, 256 * 256 / 4);
    cvt_f2h<<<(1024 * 256 / 4 + 255) / 256, 256>>>(fc1_w, wfc1, 1024 * 256 / 4);
    cvt_f2h<<<(256 * 1024 / 4 + 255) / 256, 256>>>(fc2_w, wfc2, 256 * 1024 / 4);

    ln1_window_kernel<<<NTOK / 8, 256>>>(x, n1g, n1b, xwh);

    gemm_f16k<0><<<dim3(768 / TN, NTOK / TM), 256, GEMM_SMEM_BYTES>>>(
        xwh, wqkv, qkv_b, qkvb, NTOK, 768, CC, nullptr);

    attn_kernel<<<dim3(BWIN, HEADS), 256>>>(qkvb, rpb_tab, amask, sal_fg, sal_bg, obufh);

    gemm_f16k<3><<<dim3(CC / TN, NTOK / TM), 256, GEMM_SMEM_BYTES>>>(
        obufh, wproj, proj_b, x2, NTOK, CC, CC, x);

    ln2_kernel<<<NTOK / 8, 256>>>(x2, n2g, n2b, xn2h);

    gemm_f16k<1><<<dim3(1024 / TN, NTOK / TM), 256, GEMM_SMEM_BYTES>>>(
        xn2h, wfc1, fc1_b, h1h, NTOK, 1024, CC, nullptr);

    gemm_f16k<2><<<dim3(CC / TN, NTOK / TM), 256, GEMM_SMEM_BYTES>>>(
        h1h, wfc2, fc2_b, out, NTOK, CC, 1024, x2);
}

// round 15
// speedup vs baseline: 3.6287x; 1.1375x over previous
#include <cuda_runtime.h>
#include <cuda_fp16.h>
#include <math.h>
#include <cstdint>

// ---------------- problem constants ----------------
#define BB    32
#define HH    56
#define WW    56
#define CC    256
#define WIN   7
#define SHIFT 3
#define HEADS 8
#define HD    32
#define NN    49
#define NWIN  64
#define BWIN  (BB*NWIN)   // 2048
#define NTOK  (BWIN*NN)   // 100352
#define LL    (HH*WW)     // 3136

// ---------------- scratch ----------------
__device__ __half g_xwh [(size_t)NTOK*CC];       // LN1 out (fp16)
__device__ __half g_qkvh[(size_t)NTOK*3*CC];     // qkv gemm out (fp16)
__device__ __half g_obufh[(size_t)NTOK*CC];      // attention out (fp16)
__device__ float  g_x2  [(size_t)BB*LL*CC];      // residual stream (fp32)
__device__ __half g_xn2h[(size_t)NTOK*CC];       // LN2 out (fp16)
__device__ __half g_h1h [(size_t)NTOK*4*CC];     // fc1+gelu out (fp16)
// fp16 weights (converted per launch)
__device__ __half g_wqkv[768*256];
__device__ __half g_wproj[256*256];
__device__ __half g_wfc1[1024*256];
__device__ __half g_wfc2[256*1024];

// ---------------- helpers ----------------
__device__ __forceinline__ float warp_sum(float v) {
#pragma unroll
    for (int o = 16; o; o >>= 1) v += __shfl_xor_sync(0xffffffffu, v, o);
    return v;
}
__device__ __forceinline__ float warp_max(float v) {
#pragma unroll
    for (int o = 16; o; o >>= 1) v = fmaxf(v, __shfl_xor_sync(0xffffffffu, v, o));
    return v;
}
__device__ __forceinline__ uint32_t smem_u32(const void* p) {
    uint32_t a;
    asm("{ .reg .u64 t; cvta.to.shared.u64 t, %1; cvt.u32.u64 %0, t; }" : "=r"(a) : "l"(p));
    return a;
}
__device__ __forceinline__ int tok_to_imgrow(int tok) {
    int n  = tok % NN;
    int bw = tok / NN;
    int b  = bw >> 6;
    int w  = bw & 63;
    int hs = (w >> 3) * WIN + n / WIN;
    int ws = (w & 7)  * WIN + n % WIN;
    int h0 = hs + SHIFT; if (h0 >= HH) h0 -= HH;
    int w0 = ws + SHIFT; if (w0 >= WW) w0 -= WW;
    return b * LL + h0 * WW + w0;
}

#define CP_ASYNC16(dst, src) \
    asm volatile("cp.async.cg.shared.global [%0], [%1], 16;" :: "r"(dst), "l"(src))
#define CP_COMMIT() asm volatile("cp.async.commit_group;" ::: "memory")
#define CP_WAIT(n)  asm volatile("cp.async.wait_group %0;" :: "n"(n) : "memory")
#define LDSM4(r0, r1, r2, r3, addr) \
    asm volatile("ldmatrix.sync.aligned.m8n8.x4.shared.b16 {%0,%1,%2,%3}, [%4];" \
                 : "=r"(r0), "=r"(r1), "=r"(r2), "=r"(r3) : "r"(addr))

__device__ __forceinline__ void mma_f16(float* c, const uint32_t* a, const uint32_t* b) {
    asm volatile(
        "mma.sync.aligned.m16n8k16.row.col.f32.f16.f16.f32 "
        "{%0,%1,%2,%3}, {%4,%5,%6,%7}, {%8,%9}, {%0,%1,%2,%3};"
        : "+f"(c[0]), "+f"(c[1]), "+f"(c[2]), "+f"(c[3])
        : "r"(a[0]), "r"(a[1]), "r"(a[2]), "r"(a[3]), "r"(b[0]), "r"(b[1]));
}

// ---------------- weight conversion ----------------
__global__ void cvt_f2h(const float* __restrict__ in, __half* __restrict__ out, int n4) {
    int i = blockIdx.x * 256 + threadIdx.x;
    if (i >= n4) return;
    float4 v = ((const float4*)in)[i];
    __half2* o = (__half2*)(out + (size_t)i * 4);
    o[0] = __floats2half2_rn(v.x, v.y);
    o[1] = __floats2half2_rn(v.z, v.w);
}

// ---------------- LN kernels (fp32 in -> fp16 out) ----------------
__global__ void ln1_window_kernel(const float* __restrict__ x,
                                  const float* __restrict__ g,
                                  const float* __restrict__ b,
                                  __half* __restrict__ xw) {
    int tok  = blockIdx.x * 8 + (threadIdx.x >> 5);
    int lane = threadIdx.x & 31;
    if (tok >= NTOK) return;
    const float* row = x + (size_t)tok_to_imgrow(tok) * CC;
    float vals[8], s = 0.f;
#pragma unroll
    for (int q = 0; q < 8; q++) { vals[q] = row[lane + 32 * q]; s += vals[q]; }
    float mean = warp_sum(s) * (1.f / CC);
    float vv = 0.f;
#pragma unroll
    for (int q = 0; q < 8; q++) { float d = vals[q] - mean; vv += d * d; }
    float inv = rsqrtf(warp_sum(vv) * (1.f / CC) + 1e-5f);
    __half* out = xw + (size_t)tok * CC;
#pragma unroll
    for (int q = 0; q < 8; q++) {
        int c = lane + 32 * q;
        out[c] = __float2half_rn((vals[q] - mean) * inv * g[c] + b[c]);
    }
}
__global__ void ln2_kernel(const float* __restrict__ x,
                           const float* __restrict__ g,
                           const float* __restrict__ b,
                           __half* __restrict__ out_) {
    int tok  = blockIdx.x * 8 + (threadIdx.x >> 5);
    int lane = threadIdx.x & 31;
    if (tok >= NTOK) return;
    const float* row = x + (size_t)tok * CC;
    float vals[8], s = 0.f;
#pragma unroll
    for (int q = 0; q < 8; q++) { vals[q] = row[lane + 32 * q]; s += vals[q]; }
    float mean = warp_sum(s) * (1.f / CC);
    float vv = 0.f;
#pragma unroll
    for (int q = 0; q < 8; q++) { float d = vals[q] - mean; vv += d * d; }
    float inv = rsqrtf(warp_sum(vv) * (1.f / CC) + 1e-5f);
    __half* out = out_ + (size_t)tok * CC;
#pragma unroll
    for (int q = 0; q < 8; q++) {
        int c = lane + 32 * q;
        out[c] = __float2half_rn((vals[q] - mean) * inv * g[c] + b[c]);
    }
}

// ---------------- fp16 m16n8k16 GEMM, ldmatrix + TK=64 ----------------
// Block tile 64x128, warp tile 32x32, 8 warps, 3 CTAs/SM.
// MODE 0 plain->f16 | 1 GELU->f16 | 2 +res->f32 | 3 scatter+res->f32
#define TM 64
#define TN 128
#define TK 64
#define ROWB 144                          // 128B data + 16B pad per 64-half row
#define A_BYTES (TM * ROWB)               // 9216
#define B_BYTES (TN * ROWB)               // 18432
#define STAGE_BYTES (A_BYTES + B_BYTES)   // 27648
#define GEMM_SMEM_BYTES (2 * STAGE_BYTES) // 55296

template <int MODE>
__global__ __launch_bounds__(256, 3)
void gemm_f16k(const __half* __restrict__ A, const __half* __restrict__ W,
               const float* __restrict__ bias, void* __restrict__ Cv,
               int M, int N, int K, const float* __restrict__ res) {
    extern __shared__ __align__(128) char smem[];
    uint32_t sb = smem_u32(smem);
    int tid = threadIdx.x, wid = tid >> 5, lane = tid & 31;
    int wm = wid >> 2, wn = wid & 3;          // 2 x 4 warp grid, warp tile 32x32
    int m0 = blockIdx.y * TM, n0 = blockIdx.x * TN;
    int g  = lane >> 2, p = lane & 3;

    float acc[2][4][4];
#pragma unroll
    for (int i = 0; i < 2; i++)
#pragma unroll
        for (int j = 0; j < 4; j++)
#pragma unroll
            for (int r = 0; r < 4; r++) acc[i][j][r] = 0.f;

    // cp.async mapping: rows of 128B = 8 chunks of 16B
    int lrow = tid >> 3;            // 0..31
    int lchk = tid & 7;
    const __half* gA = A + (size_t)(m0 + lrow) * K + lchk * 8;
    const __half* gW = W + (size_t)(n0 + lrow) * K + lchk * 8;
    uint32_t dA = sb + lrow * ROWB + lchk * 16;
    uint32_t dB = sb + A_BYTES + lrow * ROWB + lchk * 16;

    // ldmatrix base addresses (per lane)
    uint32_t aAddr = sb + (uint32_t)(wm * 32 + (lane & 15)) * ROWB + (lane >> 4) * 16;
    uint32_t bAddr = sb + A_BYTES +
                     (uint32_t)(wn * 32 + (lane & 7) + (lane >> 4) * 8) * ROWB +
                     ((lane >> 3) & 1) * 16;

    int KT = K / TK;
    // prologue: stage 0
#pragma unroll
    for (int q = 0; q < 2; q++)
        CP_ASYNC16(dA + q * 32 * ROWB, gA + (size_t)q * 32 * K);
#pragma unroll
    for (int q = 0; q < 4; q++)
        CP_ASYNC16(dB + q * 32 * ROWB, gW + (size_t)q * 32 * K);
    CP_COMMIT();

#pragma unroll 1
    for (int kt = 0; kt < KT; kt++) {
        bool more = (kt + 1 < KT);
        if (more) {
            uint32_t off = ((kt + 1) & 1) * STAGE_BYTES;
            const __half* sA = gA + (size_t)(kt + 1) * TK;
            const __half* sW = gW + (size_t)(kt + 1) * TK;
#pragma unroll
            for (int q = 0; q < 2; q++)
                CP_ASYNC16(dA + off + q * 32 * ROWB, sA + (size_t)q * 32 * K);
#pragma unroll
            for (int q = 0; q < 4; q++)
                CP_ASYNC16(dB + off + q * 32 * ROWB, sW + (size_t)q * 32 * K);
            CP_COMMIT();
            CP_WAIT(1);
        } else {
            CP_WAIT(0);
        }
        __syncthreads();

        uint32_t stg = ((uint32_t)kt & 1) * STAGE_BYTES;
#pragma unroll
        for (int ks = 0; ks < 4; ks++) {
            uint32_t kb = ks * 32;   // 16 halves = 32 bytes per ks step
            uint32_t af[2][4], bf[4][2];
#pragma unroll
            for (int i = 0; i < 2; i++)
                LDSM4(af[i][0], af[i][1], af[i][2], af[i][3],
                      aAddr + stg + i * 16 * ROWB + kb);
#pragma unroll
            for (int j2 = 0; j2 < 2; j2++)
                LDSM4(bf[2 * j2][0], bf[2 * j2][1], bf[2 * j2 + 1][0], bf[2 * j2 + 1][1],
                      bAddr + stg + j2 * 16 * ROWB + kb);
#pragma unroll
            for (int i = 0; i < 2; i++)
#pragma unroll
                for (int j = 0; j < 4; j++)
                    mma_f16(acc[i][j], af[i], bf[j]);
        }
        __syncthreads();
    }

    // epilogue
#pragma unroll
    for (int i = 0; i < 2; i++) {
#pragma unroll
        for (int half_ = 0; half_ < 2; half_++) {
            int m = m0 + wm * 32 + i * 16 + g + half_ * 8;
            size_t rout = (size_t)m;
            if (MODE == 3) rout = (size_t)tok_to_imgrow(m);
#pragma unroll
            for (int j = 0; j < 4; j++) {
                int col = n0 + wn * 32 + j * 8 + 2 * p;
                float v0 = acc[i][j][half_ * 2 + 0] + bias[col];
                float v1 = acc[i][j][half_ * 2 + 1] + bias[col + 1];
                if (MODE == 0) {
                    *(__half2*)((__half*)Cv + rout * N + col) = __floats2half2_rn(v0, v1);
                } else if (MODE == 1) {
                    v0 = 0.5f * v0 * (1.f + erff(v0 * 0.7071067811865476f));
                    v1 = 0.5f * v1 * (1.f + erff(v1 * 0.7071067811865476f));
                    *(__half2*)((__half*)Cv + rout * N + col) = __floats2half2_rn(v0, v1);
                } else {
                    if (MODE == 2) {
                        v0 += res[(size_t)m * N + col];
                        v1 += res[(size_t)m * N + col + 1];
                    }
                    if (MODE == 3) {
                        v0 += res[rout * N + col];
                        v1 += res[rout * N + col + 1];
                    }
                    *(float2*)((float*)Cv + rout * N + col) = make_float2(v0, v1);
                }
            }
        }
    }
}

// ---------------- K3: windowed attention, triple softmax --------------------
#define QP 33
__global__ __launch_bounds__(256)
void attn_kernel(const __half* __restrict__ qkv,
                 const float* __restrict__ rpb_table,
                 const float* __restrict__ attn_mask,
                 const float* __restrict__ sal_fg,
                 const float* __restrict__ sal_bg,
                 __half* __restrict__ obuf) {
    int bw = blockIdx.x;
    int h  = blockIdx.y;
    int tid  = threadIdx.x;
    int lane = tid & 31;
    int warp = tid >> 5;

    __shared__ float qs[NN * QP];
    __shared__ float ks[NN * QP];
    __shared__ float vs[NN * QP];
    __shared__ float sc[NN * NN];
    __shared__ float rpb_s[169];
    __shared__ float fg_s[NN], bg_s[NN];

    const __half* base = qkv + (size_t)bw * NN * (3 * CC);
    const float scale = 0.17677669529663687f;
    for (int t = tid; t < NN * HD; t += 256) {
        int n = t >> 5, dd = t & 31;
        qs[n * QP + dd] = __half2float(base[n * 768 +          h * HD + dd]) * scale;
        ks[n * QP + dd] = __half2float(base[n * 768 + CC     + h * HD + dd]);
        vs[n * QP + dd] = __half2float(base[n * 768 + 2 * CC + h * HD + dd]);
    }
    if (tid < 169) rpb_s[tid] = rpb_table[tid * HEADS + h];
    if (tid < NN) {
        fg_s[tid] = sal_fg[(size_t)bw * (NN * NN) + tid];
        bg_s[tid] = sal_bg[(size_t)bw * (NN * NN) + tid];
    }
    __syncthreads();

    int w = bw & 63;
    const float* am = attn_mask + (size_t)w * (NN * NN);
    for (int t = tid; t < NN * NN; t += 256) {
        int i = t / NN, j = t - i * NN;
        float s = 0.f;
        const float* qi = qs + i * QP;
        const float* kj = ks + j * QP;
#pragma unroll
        for (int dd = 0; dd < HD; dd++) s += qi[dd] * kj[dd];
        int dy = i / WIN - j / WIN + (WIN - 1);
        int dx = i % WIN - j % WIN + (WIN - 1);
        sc[t] = s + rpb_s[dy * (2 * WIN - 1) + dx] + am[t];
    }
    __syncthreads();

    for (int i = warp; i < NN; i += 8) {
        float* rowp = sc + i * NN;
        float a0 = rowp[lane];
        bool v1  = (lane + 32) < NN;
        float a1 = v1 ? rowp[lane + 32] : -1e30f;
        float f0 = fg_s[lane], b0m = bg_s[lane];
        float f1 = v1 ? fg_s[lane + 32] : 0.f;
        float b1m = v1 ? bg_s[lane + 32] : 0.f;

        float m1 = warp_max(fmaxf(a0, a1));
        float m2 = warp_max(fmaxf(a0 + f0, v1 ? a1 + f1 : -1e30f));
        float m3 = warp_max(fmaxf(a0 + b0m, v1 ? a1 + b1m : -1e30f));

        float e1a = __expf(a0 - m1),       e1b = v1 ? __expf(a1 - m1) : 0.f;
        float e2a = __expf(a0 + f0 - m2),  e2b = v1 ? __expf(a1 + f1 - m2) : 0.f;
        float e3a = __expf(a0 + b0m - m3), e3b = v1 ? __expf(a1 + b1m - m3) : 0.f;

        float i1 = 1.f / warp_sum(e1a + e1b);
        float i2 = 1.f / warp_sum(e2a + e2b);
        float i3 = 1.f / warp_sum(e3a + e3b);

        rowp[lane] = e1a * i1 + e2a * i2 - e3a * i3;
        if (v1) rowp[lane + 32] = e1b * i1 + e2b * i2 - e3b * i3;
    }
    __syncthreads();

    for (int t = tid; t < NN * HD; t += 256) {
        int i = t >> 5, dd = t & 31;
        const float* wrow = sc + i * NN;
        float acc = 0.f;
#pragma unroll
        for (int j = 0; j < NN; j++) acc += wrow[j] * vs[j * QP + dd];
        obuf[((size_t)bw * NN + i) * CC + h * HD + dd] = __float2half_rn(acc);
    }
}

// ---------------- launch ----------------
extern "C" void kernel_launch(void* const* d_in, const int* in_sizes, int n_in,
                              void* d_out, int out_size) {
    const float* x       = (const float*)d_in[0];
    const float* qkv_w   = (const float*)d_in[1];
    const float* qkv_b   = (const float*)d_in[2];
    const float* rpb_tab = (const float*)d_in[3];
    const float* proj_w  = (const float*)d_in[4];
    const float* proj_b  = (const float*)d_in[5];
    const float* n1g     = (const float*)d_in[6];
    const float* n1b     = (const float*)d_in[7];
    const float* n2g     = (const float*)d_in[8];
    const float* n2b     = (const float*)d_in[9];
    const float* fc1_w   = (const float*)d_in[10];
    const float* fc1_b   = (const float*)d_in[11];
    const float* fc2_w   = (const float*)d_in[12];
    const float* fc2_b   = (const float*)d_in[13];
    const float* amask   = (const float*)d_in[14];
    const float* sal_fg  = (const float*)d_in[15];
    const float* sal_bg  = (const float*)d_in[16];
    float* out = (float*)d_out;

    __half *xwh, *qkvh, *obufh, *xn2h, *h1h, *wqkv, *wproj, *wfc1, *wfc2;
    float *x2;
    cudaGetSymbolAddress((void**)&xwh,   g_xwh);
    cudaGetSymbolAddress((void**)&qkvh,  g_qkvh);
    cudaGetSymbolAddress((void**)&obufh, g_obufh);
    cudaGetSymbolAddress((void**)&x2,    g_x2);
    cudaGetSymbolAddress((void**)&xn2h,  g_xn2h);
    cudaGetSymbolAddress((void**)&h1h,   g_h1h);
    cudaGetSymbolAddress((void**)&wqkv,  g_wqkv);
    cudaGetSymbolAddress((void**)&wproj, g_wproj);
    cudaGetSymbolAddress((void**)&wfc1,  g_wfc1);
    cudaGetSymbolAddress((void**)&wfc2,  g_wfc2);

    static bool attr_done = false;
    if (!attr_done) {
        cudaFuncSetAttribute(gemm_f16k<0>, cudaFuncAttributeMaxDynamicSharedMemorySize, GEMM_SMEM_BYTES);
        cudaFuncSetAttribute(gemm_f16k<1>, cudaFuncAttributeMaxDynamicSharedMemorySize, GEMM_SMEM_BYTES);
        cudaFuncSetAttribute(gemm_f16k<2>, cudaFuncAttributeMaxDynamicSharedMemorySize, GEMM_SMEM_BYTES);
        cudaFuncSetAttribute(gemm_f16k<3>, cudaFuncAttributeMaxDynamicSharedMemorySize, GEMM_SMEM_BYTES);
        attr_done = true;
    }

    cvt_f2h<<<(768 * 256 / 4 + 255) / 256, 256>>>(qkv_w, wqkv, 768 * 256 / 4);
    cvt_f2h<<<(256 * 256 / 4 + 255) / 256, 256>>>(proj_w, wproj, 256 * 256 / 4);
    cvt_f2h<<<(1024 * 256 / 4 + 255) / 256, 256>>>(fc1_w, wfc1, 1024 * 256 / 4);
    cvt_f2h<<<(256 * 1024 / 4 + 255) / 256, 256>>>(fc2_w, wfc2, 256 * 1024 / 4);

    ln1_window_kernel<<<NTOK / 8, 256>>>(x, n1g, n1b, xwh);

    gemm_f16k<0><<<dim3(768 / TN, NTOK / TM), 256, GEMM_SMEM_BYTES>>>(
        xwh, wqkv, qkv_b, qkvh, NTOK, 768, CC, nullptr);

    attn_kernel<<<dim3(BWIN, HEADS), 256>>>(qkvh, rpb_tab, amask, sal_fg, sal_bg, obufh);

    gemm_f16k<3><<<dim3(CC / TN, NTOK / TM), 256, GEMM_SMEM_BYTES>>>(
        obufh, wproj, proj_b, x2, NTOK, CC, CC, x);

    ln2_kernel<<<NTOK / 8, 256>>>(x2, n2g, n2b, xn2h);

    gemm_f16k<1><<<dim3(1024 / TN, NTOK / TM), 256, GEMM_SMEM_BYTES>>>(
        xn2h, wfc1, fc1_b, h1h, NTOK, 1024, CC, nullptr);

    gemm_f16k<2><<<dim3(CC / TN, NTOK / TM), 256, GEMM_SMEM_BYTES>>>(
        h1h, wfc2, fc2_b, out, NTOK, CC, 1024, x2);
}

// round 16
// speedup vs baseline: 3.6922x; 1.0175x over previous
#include <cuda_runtime.h>
#include <cuda_fp16.h>
#include <math.h>
#include <cstdint>

// ---------------- problem constants ----------------
#define BB    32
#define HH    56
#define WW    56
#define CC    256
#define WIN   7
#define SHIFT 3
#define HEADS 8
#define HD    32
#define NN    49
#define NWIN  64
#define BWIN  (BB*NWIN)   // 2048
#define NTOK  (BWIN*NN)   // 100352
#define LL    (HH*WW)     // 3136

// ---------------- scratch ----------------
__device__ __half g_xwh [(size_t)NTOK*CC];
__device__ __half g_qkvh[(size_t)NTOK*3*CC];
__device__ __half g_obufh[(size_t)NTOK*CC];
__device__ float  g_x2  [(size_t)BB*LL*CC];
__device__ __half g_xn2h[(size_t)NTOK*CC];
__device__ __half g_h1h [(size_t)NTOK*4*CC];
__device__ __half g_wqkv[768*256];
__device__ __half g_wproj[256*256];
__device__ __half g_wfc1[1024*256];
__device__ __half g_wfc2[256*1024];

// ---------------- helpers ----------------
__device__ __forceinline__ float warp_sum(float v) {
#pragma unroll
    for (int o = 16; o; o >>= 1) v += __shfl_xor_sync(0xffffffffu, v, o);
    return v;
}
__device__ __forceinline__ float warp_max(float v) {
#pragma unroll
    for (int o = 16; o; o >>= 1) v = fmaxf(v, __shfl_xor_sync(0xffffffffu, v, o));
    return v;
}
__device__ __forceinline__ uint32_t smem_u32(const void* p) {
    uint32_t a;
    asm("{ .reg .u64 t; cvta.to.shared.u64 t, %1; cvt.u32.u64 %0, t; }" : "=r"(a) : "l"(p));
    return a;
}
__device__ __forceinline__ int tok_to_imgrow(int tok) {
    int n  = tok % NN;
    int bw = tok / NN;
    int b  = bw >> 6;
    int w  = bw & 63;
    int hs = (w >> 3) * WIN + n / WIN;
    int ws = (w & 7)  * WIN + n % WIN;
    int h0 = hs + SHIFT; if (h0 >= HH) h0 -= HH;
    int w0 = ws + SHIFT; if (w0 >= WW) w0 -= WW;
    return b * LL + h0 * WW + w0;
}

#define CP_ASYNC16(dst, src) \
    asm volatile("cp.async.cg.shared.global [%0], [%1], 16;" :: "r"(dst), "l"(src))
#define CP_COMMIT() asm volatile("cp.async.commit_group;" ::: "memory")
#define CP_WAIT(n)  asm volatile("cp.async.wait_group %0;" :: "n"(n) : "memory")
#define LDSM4(r0, r1, r2, r3, addr) \
    asm volatile("ldmatrix.sync.aligned.m8n8.x4.shared.b16 {%0,%1,%2,%3}, [%4];" \
                 : "=r"(r0), "=r"(r1), "=r"(r2), "=r"(r3) : "r"(addr))

__device__ __forceinline__ void mma_f16(float* c, const uint32_t* a, const uint32_t* b) {
    asm volatile(
        "mma.sync.aligned.m16n8k16.row.col.f32.f16.f16.f32 "
        "{%0,%1,%2,%3}, {%4,%5,%6,%7}, {%8,%9}, {%0,%1,%2,%3};"
        : "+f"(c[0]), "+f"(c[1]), "+f"(c[2]), "+f"(c[3])
        : "r"(a[0]), "r"(a[1]), "r"(a[2]), "r"(a[3]), "r"(b[0]), "r"(b[1]));
}

// ---------------- merged weight conversion ----------------
// segments in float4 units: qkv 49152 | proj 16384 | fc1 65536 | fc2 65536
__global__ void cvt_all(const float* __restrict__ w0, const float* __restrict__ w1,
                        const float* __restrict__ w2, const float* __restrict__ w3,
                        __half* __restrict__ o0, __half* __restrict__ o1,
                        __half* __restrict__ o2, __half* __restrict__ o3) {
    int i = blockIdx.x * 256 + threadIdx.x;
    const float* src; __half* dst; int k;
    if (i < 49152)       { src = w0; dst = o0; k = i; }
    else if (i < 65536)  { src = w1; dst = o1; k = i - 49152; }
    else if (i < 131072) { src = w2; dst = o2; k = i - 65536; }
    else                 { src = w3; dst = o3; k = i - 131072; }
    float4 v = ((const float4*)src)[k];
    __half2* o = (__half2*)(dst + (size_t)k * 4);
    o[0] = __floats2half2_rn(v.x, v.y);
    o[1] = __floats2half2_rn(v.z, v.w);
}

// ---------------- LN kernels (fp32 in -> fp16 out) ----------------
__global__ void ln1_window_kernel(const float* __restrict__ x,
                                  const float* __restrict__ g,
                                  const float* __restrict__ b,
                                  __half* __restrict__ xw) {
    int tok  = blockIdx.x * 8 + (threadIdx.x >> 5);
    int lane = threadIdx.x & 31;
    if (tok >= NTOK) return;
    const float* row = x + (size_t)tok_to_imgrow(tok) * CC;
    float vals[8], s = 0.f;
#pragma unroll
    for (int q = 0; q < 8; q++) { vals[q] = row[lane + 32 * q]; s += vals[q]; }
    float mean = warp_sum(s) * (1.f / CC);
    float vv = 0.f;
#pragma unroll
    for (int q = 0; q < 8; q++) { float d = vals[q] - mean; vv += d * d; }
    float inv = rsqrtf(warp_sum(vv) * (1.f / CC) + 1e-5f);
    __half* out = xw + (size_t)tok * CC;
#pragma unroll
    for (int q = 0; q < 8; q++) {
        int c = lane + 32 * q;
        out[c] = __float2half_rn((vals[q] - mean) * inv * g[c] + b[c]);
    }
}
__global__ void ln2_kernel(const float* __restrict__ x,
                           const float* __restrict__ g,
                           const float* __restrict__ b,
                           __half* __restrict__ out_) {
    int tok  = blockIdx.x * 8 + (threadIdx.x >> 5);
    int lane = threadIdx.x & 31;
    if (tok >= NTOK) return;
    const float* row = x + (size_t)tok * CC;
    float vals[8], s = 0.f;
#pragma unroll
    for (int q = 0; q < 8; q++) { vals[q] = row[lane + 32 * q]; s += vals[q]; }
    float mean = warp_sum(s) * (1.f / CC);
    float vv = 0.f;
#pragma unroll
    for (int q = 0; q < 8; q++) { float d = vals[q] - mean; vv += d * d; }
    float inv = rsqrtf(warp_sum(vv) * (1.f / CC) + 1e-5f);
    __half* out = out_ + (size_t)tok * CC;
#pragma unroll
    for (int q = 0; q < 8; q++) {
        int c = lane + 32 * q;
        out[c] = __float2half_rn((vals[q] - mean) * inv * g[c] + b[c]);
    }
}

// ---------------- fp16 m16n8k16 GEMM, ldmatrix, TM=128, TK=64 --------------
// Block tile 128x128, warp tile 64x32, 8 warps, 2 CTAs/SM.
// MODE 0 plain->f16 | 1 GELU->f16 | 2 +res->f32 | 3 scatter+res->f32
#define TM 128
#define TN 128
#define TK 64
#define ROWB 144
#define A_BYTES (TM * ROWB)               // 18432
#define B_BYTES (TN * ROWB)               // 18432
#define STAGE_BYTES (A_BYTES + B_BYTES)   // 36864
#define GEMM_SMEM_BYTES (2 * STAGE_BYTES) // 73728

template <int MODE>
__global__ __launch_bounds__(256, 2)
void gemm_f16k(const __half* __restrict__ A, const __half* __restrict__ W,
               const float* __restrict__ bias, void* __restrict__ Cv,
               int M, int N, int K, const float* __restrict__ res) {
    extern __shared__ __align__(128) char smem[];
    uint32_t sb = smem_u32(smem);
    int tid = threadIdx.x, wid = tid >> 5, lane = tid & 31;
    int wm = wid >> 2, wn = wid & 3;          // 2x4 warp grid, warp tile 64x32
    int m0 = blockIdx.y * TM, n0 = blockIdx.x * TN;
    int g  = lane >> 2, p = lane & 3;

    float acc[4][4][4];
#pragma unroll
    for (int i = 0; i < 4; i++)
#pragma unroll
        for (int j = 0; j < 4; j++)
#pragma unroll
            for (int r = 0; r < 4; r++) acc[i][j][r] = 0.f;

    // cp.async: rows of 128B = 8 chunks of 16B; 4 row groups each for A,B
    int lrow = tid >> 3;            // 0..31
    int lchk = tid & 7;
    const __half* gA = A + (size_t)(m0 + lrow) * K + lchk * 8;
    const __half* gW = W + (size_t)(n0 + lrow) * K + lchk * 8;
    uint32_t dA = sb + lrow * ROWB + lchk * 16;
    uint32_t dB = sb + A_BYTES + lrow * ROWB + lchk * 16;

    // ldmatrix base addresses
    uint32_t aAddr = sb + (uint32_t)(wm * 64 + (lane & 15)) * ROWB + (lane >> 4) * 16;
    uint32_t bAddr = sb + A_BYTES +
                     (uint32_t)(wn * 32 + (lane & 7) + (lane >> 4) * 8) * ROWB +
                     ((lane >> 3) & 1) * 16;

    int KT = K / TK;
#pragma unroll
    for (int q = 0; q < 4; q++) {
        CP_ASYNC16(dA + q * 32 * ROWB, gA + (size_t)q * 32 * K);
        CP_ASYNC16(dB + q * 32 * ROWB, gW + (size_t)q * 32 * K);
    }
    CP_COMMIT();

#pragma unroll 1
    for (int kt = 0; kt < KT; kt++) {
        bool more = (kt + 1 < KT);
        if (more) {
            uint32_t off = ((kt + 1) & 1) * STAGE_BYTES;
            const __half* sA = gA + (size_t)(kt + 1) * TK;
            const __half* sW = gW + (size_t)(kt + 1) * TK;
#pragma unroll
            for (int q = 0; q < 4; q++) {
                CP_ASYNC16(dA + off + q * 32 * ROWB, sA + (size_t)q * 32 * K);
                CP_ASYNC16(dB + off + q * 32 * ROWB, sW + (size_t)q * 32 * K);
            }
            CP_COMMIT();
            CP_WAIT(1);
        } else {
            CP_WAIT(0);
        }
        __syncthreads();

        uint32_t stg = ((uint32_t)kt & 1) * STAGE_BYTES;
#pragma unroll
        for (int ks = 0; ks < 4; ks++) {
            uint32_t kb = ks * 32;   // 16 halves per step
            uint32_t af[4][4], bf[4][2];
#pragma unroll
            for (int i = 0; i < 4; i++)
                LDSM4(af[i][0], af[i][1], af[i][2], af[i][3],
                      aAddr + stg + i * 16 * ROWB + kb);
#pragma unroll
            for (int j2 = 0; j2 < 2; j2++)
                LDSM4(bf[2 * j2][0], bf[2 * j2][1], bf[2 * j2 + 1][0], bf[2 * j2 + 1][1],
                      bAddr + stg + j2 * 16 * ROWB + kb);
#pragma unroll
            for (int i = 0; i < 4; i++)
#pragma unroll
                for (int j = 0; j < 4; j++)
                    mma_f16(acc[i][j], af[i], bf[j]);
        }
        __syncthreads();
    }

    // epilogue
#pragma unroll
    for (int i = 0; i < 4; i++) {
#pragma unroll
        for (int half_ = 0; half_ < 2; half_++) {
            int m = m0 + wm * 64 + i * 16 + g + half_ * 8;
            size_t rout = (size_t)m;
            if (MODE == 3) rout = (size_t)tok_to_imgrow(m);
#pragma unroll
            for (int j = 0; j < 4; j++) {
                int col = n0 + wn * 32 + j * 8 + 2 * p;
                float v0 = acc[i][j][half_ * 2 + 0] + bias[col];
                float v1 = acc[i][j][half_ * 2 + 1] + bias[col + 1];
                if (MODE == 0) {
                    *(__half2*)((__half*)Cv + rout * N + col) = __floats2half2_rn(v0, v1);
                } else if (MODE == 1) {
                    v0 = 0.5f * v0 * (1.f + erff(v0 * 0.7071067811865476f));
                    v1 = 0.5f * v1 * (1.f + erff(v1 * 0.7071067811865476f));
                    *(__half2*)((__half*)Cv + rout * N + col) = __floats2half2_rn(v0, v1);
                } else {
                    if (MODE == 2) {
                        v0 += res[(size_t)m * N + col];
                        v1 += res[(size_t)m * N + col + 1];
                    }
                    if (MODE == 3) {
                        v0 += res[rout * N + col];
                        v1 += res[rout * N + col + 1];
                    }
                    *(float2*)((float*)Cv + rout * N + col) = make_float2(v0, v1);
                }
            }
        }
    }
}

// ---------------- K3: windowed attention, single-exp triple softmax ---------
#define QP2 34   // even padded stride: float2-aligned rows, conflict-free
__global__ __launch_bounds__(256)
void attn_kernel(const __half* __restrict__ qkv,
                 const float* __restrict__ rpb_table,
                 const float* __restrict__ attn_mask,
                 const float* __restrict__ sal_fg,
                 __half* __restrict__ obuf) {
    int bw = blockIdx.x;
    int h  = blockIdx.y;
    int tid  = threadIdx.x;
    int lane = tid & 31;
    int warp = tid >> 5;

    __shared__ float qs[NN * QP2];
    __shared__ float ks[NN * QP2];
    __shared__ float vs[NN * QP2];
    __shared__ float sc[NN * NN];
    __shared__ float rpb_s[169];
    __shared__ float fg_s[NN];

    const __half* base = qkv + (size_t)bw * NN * (3 * CC);
    const float scale = 0.17677669529663687f;
    for (int t = tid; t < NN * HD; t += 256) {
        int n = t >> 5, dd = t & 31;
        qs[n * QP2 + dd] = __half2float(base[n * 768 +          h * HD + dd]) * scale;
        ks[n * QP2 + dd] = __half2float(base[n * 768 + CC     + h * HD + dd]);
        vs[n * QP2 + dd] = __half2float(base[n * 768 + 2 * CC + h * HD + dd]);
    }
    if (tid < 169) rpb_s[tid] = rpb_table[tid * HEADS + h];
    if (tid < NN) fg_s[tid] = sal_fg[(size_t)bw * (NN * NN) + tid];
    __syncthreads();

    int w = bw & 63;
    const float* am = attn_mask + (size_t)w * (NN * NN);
    for (int t = tid; t < NN * NN; t += 256) {
        int i = t / NN, j = t - i * NN;
        const float2* qi = (const float2*)(qs + i * QP2);
        const float2* kj = (const float2*)(ks + j * QP2);
        float s = 0.f;
#pragma unroll
        for (int dd = 0; dd < 16; dd++) {
            float2 a = qi[dd], b = kj[dd];
            s += a.x * b.x + a.y * b.y;
        }
        int dy = i / WIN - j / WIN + (WIN - 1);
        int dx = i % WIN - j % WIN + (WIN - 1);
        sc[t] = s + rpb_s[dy * (2 * WIN - 1) + dx] + am[t];
    }
    __syncthreads();

    // warp per row: ONE exp pass; fg/bg softmaxes share e (shift invariance,
    // exp(-100) underflows vs in-set terms). bg set = complement of fg set.
    for (int i = warp; i < NN; i += 8) {
        float* rowp = sc + i * NN;
        float a0 = rowp[lane];
        bool v1  = (lane + 32) < NN;
        float a1 = v1 ? rowp[lane + 32] : -1e30f;
        bool fg0 = (fg_s[lane] == 0.f);
        bool fg1 = v1 && (fg_s[lane + 32] == 0.f);

        float m = warp_max(fmaxf(a0, a1));
        float e0 = __expf(a0 - m);
        float e1 = v1 ? __expf(a1 - m) : 0.f;
        float s1 = warp_sum(e0 + e1);
        float sf = warp_sum((fg0 ? e0 : 0.f) + (fg1 ? e1 : 0.f));
        float sb = s1 - sf;

        float i1 = 1.f / s1;
        // per-element multipliers; fallback to base weights if a set is empty
        float addf0, addf1, subb0, subb1;
        if (sf > 0.f) {
            float invf = 1.f / sf;
            addf0 = fg0 ? invf : 0.f;
            addf1 = fg1 ? invf : 0.f;
        } else { addf0 = addf1 = i1; }
        if (sb > 0.f) {
            float invb = 1.f / sb;
            subb0 = fg0 ? 0.f : invb;
            subb1 = (v1 && !fg1) ? invb : 0.f;
        } else { subb0 = subb1 = i1; }

        rowp[lane] = e0 * (i1 + addf0 - subb0);
        if (v1) rowp[lane + 32] = e1 * (i1 + addf1 - subb1);
    }
    __syncthreads();

    // O = P @ V, two dd per thread (float2 v loads)
    __half* orow = obuf + (size_t)bw * NN * CC + h * HD;
    for (int t = tid; t < NN * (HD / 2); t += 256) {
        int i = t >> 4, ddp = t & 15;
        const float* wrow = sc + i * NN;
        float ax = 0.f, ay = 0.f;
#pragma unroll
        for (int j = 0; j < NN; j++) {
            float wv = wrow[j];
            float2 v2 = *(const float2*)(vs + j * QP2 + 2 * ddp);
            ax += wv * v2.x;
            ay += wv * v2.y;
        }
        *(__half2*)(orow + (size_t)i * CC + 2 * ddp) = __floats2half2_rn(ax, ay);
    }
}

// ---------------- launch ----------------
extern "C" void kernel_launch(void* const* d_in, const int* in_sizes, int n_in,
                              void* d_out, int out_size) {
    const float* x       = (const float*)d_in[0];
    const float* qkv_w   = (const float*)d_in[1];
    const float* qkv_b   = (const float*)d_in[2];
    const float* rpb_tab = (const float*)d_in[3];
    const float* proj_w  = (const float*)d_in[4];
    const float* proj_b  = (const float*)d_in[5];
    const float* n1g     = (const float*)d_in[6];
    const float* n1b     = (const float*)d_in[7];
    const float* n2g     = (const float*)d_in[8];
    const float* n2b     = (const float*)d_in[9];
    const float* fc1_w   = (const float*)d_in[10];
    const float* fc1_b   = (const float*)d_in[11];
    const float* fc2_w   = (const float*)d_in[12];
    const float* fc2_b   = (const float*)d_in[13];
    const float* amask   = (const float*)d_in[14];
    const float* sal_fg  = (const float*)d_in[15];
    float* out = (float*)d_out;

    __half *xwh, *qkvh, *obufh, *xn2h, *h1h, *wqkv, *wproj, *wfc1, *wfc2;
    float *x2;
    cudaGetSymbolAddress((void**)&xwh,   g_xwh);
    cudaGetSymbolAddress((void**)&qkvh,  g_qkvh);
    cudaGetSymbolAddress((void**)&obufh, g_obufh);
    cudaGetSymbolAddress((void**)&x2,    g_x2);
    cudaGetSymbolAddress((void**)&xn2h,  g_xn2h);
    cudaGetSymbolAddress((void**)&h1h,   g_h1h);
    cudaGetSymbolAddress((void**)&wqkv,  g_wqkv);
    cudaGetSymbolAddress((void**)&wproj, g_wproj);
    cudaGetSymbolAddress((void**)&wfc1,  g_wfc1);
    cudaGetSymbolAddress((void**)&wfc2,  g_wfc2);

    static bool attr_done = false;
    if (!attr_done) {
        cudaFuncSetAttribute(gemm_f16k<0>, cudaFuncAttributeMaxDynamicSharedMemorySize, GEMM_SMEM_BYTES);
        cudaFuncSetAttribute(gemm_f16k<1>, cudaFuncAttributeMaxDynamicSharedMemorySize, GEMM_SMEM_BYTES);
        cudaFuncSetAttribute(gemm_f16k<2>, cudaFuncAttributeMaxDynamicSharedMemorySize, GEMM_SMEM_BYTES);
        cudaFuncSetAttribute(gemm_f16k<3>, cudaFuncAttributeMaxDynamicSharedMemorySize, GEMM_SMEM_BYTES);
        attr_done = true;
    }

    cvt_all<<<768, 256>>>(qkv_w, proj_w, fc1_w, fc2_w, wqkv, wproj, wfc1, wfc2);

    ln1_window_kernel<<<NTOK / 8, 256>>>(x, n1g, n1b, xwh);

    gemm_f16k<0><<<dim3(768 / TN, NTOK / TM), 256, GEMM_SMEM_BYTES>>>(
        xwh, wqkv, qkv_b, qkvh, NTOK, 768, CC, nullptr);

    attn_kernel<<<dim3(BWIN, HEADS), 256>>>(qkvh, rpb_tab, amask, sal_fg, obufh);

    gemm_f16k<3><<<dim3(CC / TN, NTOK / TM), 256, GEMM_SMEM_BYTES>>>(
        obufh, wproj, proj_b, x2, NTOK, CC, CC, x);

    ln2_kernel<<<NTOK / 8, 256>>>(x2, n2g, n2b, xn2h);

    gemm_f16k<1><<<dim3(1024 / TN, NTOK / TM), 256, GEMM_SMEM_BYTES>>>(
        xn2h, wfc1, fc1_b, h1h, NTOK, 1024, CC, nullptr);

    gemm_f16k<2><<<dim3(CC / TN, NTOK / TM), 256, GEMM_SMEM_BYTES>>>(
        h1h, wfc2, fc2_b, out, NTOK, CC, 1024, x2);
}